// round 12
// baseline (speedup 1.0000x reference)
#include <cuda_runtime.h>
#include <cuda_bf16.h>
#include <cstdint>

#define BS 4
#define SEQ 4096
#define DK 128
#define SCALE 0.08838834764831843f   // 1/sqrt(128)
#define NT 32                        // 4096/128 tiles
#define NS2 8                        // split-K for output GEMM
#define SEG 4608                     // blob segment = 128 rows x 72 bf16 (144B rows)
#define TS  (4*SEG)                  // tile blob = [hi c0][hi c1][lo c0][lo c1]

// Pipelined stage: 4 parts x (128 rows x 80B) = 40960 B; two stages = 81920 B
#define RS2 80
#define PART_BYTES 10240
#define P_AH 0
#define P_AL 10240
#define P_BH 20480
#define P_BL 30720
#define STAGE_BYTES 40960
#define SMEM_BYTES 81920

// Blobs: exact padded images -> GEMM loads are raw async copies.
__device__ uint32_t g_Q[(size_t)BS*NT*TS];
__device__ uint32_t g_K[(size_t)BS*NT*TS];
__device__ uint32_t g_W[(size_t)BS*NT*TS];      // coef*V transposed [d][k]
__device__ uint32_t g_P[(size_t)BS*NT*NT*TS];   // ~300 MB
__device__ float g_colsum[BS*SEQ];
__device__ float g_part[(size_t)NS2*BS*SEQ*DK];

// ------------------------------------------------------------------ helpers
__device__ __forceinline__ uint32_t smem_u32(const void* p) {
    uint32_t a;
    asm("{ .reg .u64 t; cvta.to.shared.u64 t, %1; cvt.u32.u64 %0, t; }" : "=r"(a) : "l"(p));
    return a;
}
__device__ __forceinline__ void ldsm4(uint32_t* r, uint32_t addr) {
    asm volatile("ldmatrix.sync.aligned.m8n8.x4.shared.b16 {%0,%1,%2,%3}, [%4];"
                 : "=r"(r[0]), "=r"(r[1]), "=r"(r[2]), "=r"(r[3]) : "r"(addr));
}
// NOT volatile: register-only op; lets ptxas schedule across the group.
__device__ __forceinline__ void mma16816(float* c, const uint32_t* a, uint32_t b0, uint32_t b1) {
    asm("mma.sync.aligned.m16n8k16.row.col.f32.bf16.bf16.f32 "
        "{%0,%1,%2,%3}, {%4,%5,%6,%7}, {%8,%9}, {%0,%1,%2,%3};"
        : "+f"(c[0]), "+f"(c[1]), "+f"(c[2]), "+f"(c[3])
        : "r"(a[0]), "r"(a[1]), "r"(a[2]), "r"(a[3]), "r"(b0), "r"(b1));
}
__device__ __forceinline__ void bsplit2(float x, float y, uint32_t& h, uint32_t& l) {
    __nv_bfloat16 hx = __float2bfloat16(x), hy = __float2bfloat16(y);
    __nv_bfloat16 lx = __float2bfloat16(x - __bfloat162float(hx));
    __nv_bfloat16 ly = __float2bfloat16(y - __bfloat162float(hy));
    h = (uint32_t)__bfloat16_as_ushort(hx) | ((uint32_t)__bfloat16_as_ushort(hy) << 16);
    l = (uint32_t)__bfloat16_as_ushort(lx) | ((uint32_t)__bfloat16_as_ushort(ly) << 16);
}
__device__ __forceinline__ float bf2f(uint16_t u) {
    return __bfloat162float(__ushort_as_bfloat16(u));
}
__device__ __forceinline__ void cp16(uint32_t sdst, const void* gsrc) {
    asm volatile("cp.async.cg.shared.global [%0], [%1], 16;" :: "r"(sdst), "l"(gsrc) : "memory");
}
__device__ __forceinline__ void cp_commit() { asm volatile("cp.async.commit_group;" ::: "memory"); }
__device__ __forceinline__ void cp_wait0() { asm volatile("cp.async.wait_group 0;" ::: "memory"); }
__device__ __forceinline__ void cp_wait1() { asm volatile("cp.async.wait_group 1;" ::: "memory"); }

// Issue one 32-k sub-chunk (4 parts x 128 rows x 64B) from blobs into a stage.
// ch = 64-k chunk (0/1), h = 32-k half (0/1). 256 threads.
__device__ __forceinline__ void issue_sub(uint32_t stage, const uint32_t* Ab, const uint32_t* Bb,
                                          int ch, int h, int tid) {
    const uint32_t* segs[4] = { Ab + ch * SEG, Ab + (2 + ch) * SEG,
                                Bb + ch * SEG, Bb + (2 + ch) * SEG };
    #pragma unroll
    for (int i = 0; i < 8; i++) {
        int t = tid + i * 256;
        int part = t >> 9;           // uniform per i
        int w = t & 511, row = w >> 2, q = w & 3;
        const char* src = (const char*)segs[part] + row * 144 + h * 64 + q * 16;
        cp16(stage + part * PART_BYTES + row * RS2 + q * 16, src);
    }
    cp_commit();
}

// ---------------------------------------------------------------------------
// 3-pass bf16-split sub-chunk GEMM over 32 k (stage @sbase), 64x32 warp tile.
// MMAs grouped so 16 independent accumulators separate any acc reuse.
// ---------------------------------------------------------------------------
__device__ __forceinline__ void mma_sub(uint32_t sbase, float acc[4][4][4],
                                        int warp_m, int warp_n, int lane) {
    int rIn  = (lane & 7) + ((lane >> 3) & 1) * 8;
    int kOff = (lane >> 4) * 16;
    int aRow0 = warp_m * 64 + rIn;
    int bRow0 = warp_n * 32 + rIn;

    #pragma unroll
    for (int s = 0; s < 2; s++) {
        uint32_t a[4][4], bh[2][4], bl[2][4];
        #pragma unroll
        for (int nj = 0; nj < 2; nj++) {
            ldsm4(bh[nj], sbase + P_BH + (bRow0 + nj * 16) * RS2 + kOff + s * 32);
            ldsm4(bl[nj], sbase + P_BL + (bRow0 + nj * 16) * RS2 + kOff + s * 32);
        }
        #pragma unroll
        for (int mi = 0; mi < 4; mi++)
            ldsm4(a[mi], sbase + P_AH + (aRow0 + mi * 16) * RS2 + kOff + s * 32);

        // group 1: A_hi x B_hi — 16 independent accs
        #pragma unroll
        for (int mi = 0; mi < 4; mi++)
            #pragma unroll
            for (int ng = 0; ng < 4; ng++) {
                int nj = ng >> 1, g = ng & 1;
                mma16816(acc[mi][ng], a[mi], bh[nj][g], bh[nj][g + 2]);
            }
        // group 2: A_hi x B_lo — 16 independent accs
        #pragma unroll
        for (int mi = 0; mi < 4; mi++)
            #pragma unroll
            for (int ng = 0; ng < 4; ng++) {
                int nj = ng >> 1, g = ng & 1;
                mma16816(acc[mi][ng], a[mi], bl[nj][g], bl[nj][g + 2]);
            }
        // group 3: A_lo x B_hi — 16 independent accs
        uint32_t al[4][4];
        #pragma unroll
        for (int mi = 0; mi < 4; mi++)
            ldsm4(al[mi], sbase + P_AL + (aRow0 + mi * 16) * RS2 + kOff + s * 32);
        #pragma unroll
        for (int mi = 0; mi < 4; mi++)
            #pragma unroll
            for (int ng = 0; ng < 4; ng++) {
                int nj = ng >> 1, g = ng & 1;
                mma16816(acc[mi][ng], al[mi], bh[nj][g], bh[nj][g + 2]);
            }
    }
}

// ---------------------------------------------------------------- tiny kernels
__global__ void zero_kernel() {
    int i = blockIdx.x * blockDim.x + threadIdx.x;
    if (i < BS * SEQ) g_colsum[i] = 0.f;
}
__global__ void recip_kernel() {
    int i = blockIdx.x * blockDim.x + threadIdx.x;
    if (i < BS * SEQ) g_colsum[i] = 1.0f / g_colsum[i];
}

// ---------------------------------------------------------------------------
// Q/K f32 -> bf16 hi/lo padded blobs
// ---------------------------------------------------------------------------
__global__ __launch_bounds__(256)
void convert_qk(const float* __restrict__ Q, const float* __restrict__ K) {
    int tile = blockIdx.x, which = blockIdx.y, b = blockIdx.z;
    const float* src = (which ? K : Q) + ((size_t)b * SEQ + tile * 128) * DK;
    uint32_t* dst = (which ? g_K : g_Q) + (size_t)(b * NT + tile) * TS;

    for (int i = threadIdx.x; i < 2 * SEG; i += 256) {
        int ch = i / SEG, j = i % SEG;
        int row = j / 36, cp = j % 36;
        uint32_t h = 0, l = 0;
        if (cp < 32) {
            float2 v = *(const float2*)&src[row * DK + ch * 64 + cp * 2];
            bsplit2(v.x, v.y, h, l);
        }
        dst[ch * SEG + j] = h;
        dst[(2 + ch) * SEG + j] = l;
    }
}

// ---------------------------------------------------------------------------
// V f32 -> W blob: W[d][k] = coef_k * V[k][d], bf16 hi/lo, padded image.
// ---------------------------------------------------------------------------
__global__ __launch_bounds__(256)
void convert_v(const float* __restrict__ V) {
    int kb = blockIdx.x, b = blockIdx.y;
    const float* Vb = V + (size_t)b * SEQ * DK;
    const float* Cb = g_colsum + b * SEQ;
    uint32_t* dst = g_W + (size_t)(b * NT + kb) * TS;

    for (int i = threadIdx.x; i < 2 * SEG; i += 256) {
        int ch = i / SEG, j = i % SEG;
        int d = j / 36, kp = j % 36;
        uint32_t h = 0, l = 0;
        if (kp < 32) {
            int k = kb * 128 + ch * 64 + 2 * kp;
            float v0 = Vb[(size_t)k * DK + d]       * Cb[k];
            float v1 = Vb[(size_t)(k + 1) * DK + d] * Cb[k + 1];
            bsplit2(v0, v1, h, l);
        }
        dst[ch * SEG + j] = h;
        dst[(2 + ch) * SEG + j] = l;
    }
}

// ---------------------------------------------------------------------------
// Kernel 1: S = Q.K^T, 2-stage 32-k pipeline; epilogue exp -> P blob + colsums.
// ---------------------------------------------------------------------------
__global__ __launch_bounds__(256, 2)
void scores_hmma() {
    extern __shared__ char smem[];
    uint32_t sb = smem_u32(smem);
    int tid = threadIdx.x, lane = tid & 31, wid = tid >> 5;
    int warp_m = wid >> 2, warp_n = wid & 3;
    int kt = blockIdx.x, qt = blockIdx.y, b = blockIdx.z;

    const uint32_t* Qb = g_Q + (size_t)(b * NT + qt) * TS;
    const uint32_t* Kb = g_K + (size_t)(b * NT + kt) * TS;

    float acc[4][4][4];
    #pragma unroll
    for (int i = 0; i < 4; i++)
        #pragma unroll
        for (int j = 0; j < 4; j++)
            #pragma unroll
            for (int c = 0; c < 4; c++) acc[i][j][c] = 0.f;

    issue_sub(sb, Qb, Kb, 0, 0, tid);
    issue_sub(sb + STAGE_BYTES, Qb, Kb, 0, 1, tid);

    for (int s = 0; s < 4; s++) {
        if (s < 3) cp_wait1(); else cp_wait0();
        __syncthreads();
        mma_sub(sb + (s & 1) * STAGE_BYTES, acc, warp_m, warp_n, lane);
        __syncthreads();
        if (s + 2 < 4)
            issue_sub(sb + (s & 1) * STAGE_BYTES, Qb, Kb, (s + 2) >> 1, (s + 2) & 1, tid);
    }

    // Epilogue: exp -> bf16 hi/lo staged as blob image; colsum partials in regs.
    float cs[4][2];
    #pragma unroll
    for (int ng = 0; ng < 4; ng++) { cs[ng][0] = 0.f; cs[ng][1] = 0.f; }

    #pragma unroll
    for (int mi = 0; mi < 4; mi++)
        #pragma unroll
        for (int ng = 0; ng < 4; ng++) {
            int R = warp_m * 64 + mi * 16 + (lane >> 2);
            int C = warp_n * 32 + ng * 8 + 2 * (lane & 3);
            int ch = C >> 6, cc = C & 63;
            #pragma unroll
            for (int rr = 0; rr < 2; rr++) {
                float p0 = __expf(acc[mi][ng][rr * 2]     * SCALE);
                float p1 = __expf(acc[mi][ng][rr * 2 + 1] * SCALE);
                cs[ng][0] += p0;
                cs[ng][1] += p1;
                uint32_t h, l;
                bsplit2(p0, p1, h, l);
                int off = ch * 18432 + (R + rr * 8) * 144 + cc * 2;
                *(uint32_t*)(smem + off)         = h;
                *(uint32_t*)(smem + 36864 + off) = l;
            }
        }

    // Shuffle-reduce colsums over the 8 lanes sharing a column, then atomic.
    #pragma unroll
    for (int ng = 0; ng < 4; ng++)
        #pragma unroll
        for (int c = 0; c < 2; c++) {
            float v = cs[ng][c];
            v += __shfl_xor_sync(0xFFFFFFFF, v, 4);
            v += __shfl_xor_sync(0xFFFFFFFF, v, 8);
            v += __shfl_xor_sync(0xFFFFFFFF, v, 16);
            if ((lane >> 2) == 0) {
                int col = warp_n * 32 + ng * 8 + 2 * (lane & 3) + c;
                atomicAdd(&g_colsum[b * SEQ + kt * 128 + col], v);
            }
        }
    __syncthreads();

    // Dump the staged blob (coalesced)
    {
        size_t blob = ((size_t)(b * NT + qt) * NT + kt) * TS;
        uint4* d4 = (uint4*)(g_P + blob);
        const uint4* s4 = (const uint4*)smem;
        #pragma unroll
        for (int i = 0; i < 18; i++) d4[tid + i * 256] = s4[tid + i * 256];
    }
}

// ---------------------------------------------------------------------------
// Kernel 2: partial[split] = sum_k P~[q,k] * W~[k,d]  -> g_part
// 2-stage 32-k pipeline, 16 steps, occ 2.
// ---------------------------------------------------------------------------
__global__ __launch_bounds__(256, 2)
void out_hmma() {
    extern __shared__ char smem[];
    uint32_t sb = smem_u32(smem);
    int tid = threadIdx.x, lane = tid & 31, wid = tid >> 5;
    int warp_m = wid >> 2, warp_n = wid & 3;
    int qt = blockIdx.x, split = blockIdx.y, b = blockIdx.z;

    float acc[4][4][4];
    #pragma unroll
    for (int i = 0; i < 4; i++)
        #pragma unroll
        for (int j = 0; j < 4; j++)
            #pragma unroll
            for (int c = 0; c < 4; c++) acc[i][j][c] = 0.f;

    auto issue = [&](int s, int bi) {
        int kb = split * (NT / NS2) + (s >> 2);
        int ch = (s >> 1) & 1, h = s & 1;
        const uint32_t* Pb = g_P + ((size_t)(b * NT + qt) * NT + kb) * TS;
        const uint32_t* Wb = g_W + (size_t)(b * NT + kb) * TS;
        issue_sub(sb + bi * STAGE_BYTES, Pb, Wb, ch, h, tid);
    };

    issue(0, 0);
    issue(1, 1);

    const int NSTEP = 4 * (NT / NS2);   // 16
    for (int s = 0; s < NSTEP; s++) {
        if (s < NSTEP - 1) cp_wait1(); else cp_wait0();
        __syncthreads();
        mma_sub(sb + (s & 1) * STAGE_BYTES, acc, warp_m, warp_n, lane);
        __syncthreads();
        if (s + 2 < NSTEP) issue(s + 2, s & 1);
    }

    // Epilogue: f32 partial writes (coalesced float2)
    float* Pb = g_part + ((size_t)(split * BS + b) * SEQ + qt * 128) * DK;
    #pragma unroll
    for (int mi = 0; mi < 4; mi++)
        #pragma unroll
        for (int ng = 0; ng < 4; ng++) {
            int R = warp_m * 64 + mi * 16 + (lane >> 2);
            int C = warp_n * 32 + ng * 8 + 2 * (lane & 3);
            float2 v0 = make_float2(acc[mi][ng][0], acc[mi][ng][1]);
            float2 v1 = make_float2(acc[mi][ng][2], acc[mi][ng][3]);
            *(float2*)&Pb[(size_t)R * DK + C]       = v0;
            *(float2*)&Pb[(size_t)(R + 8) * DK + C] = v1;
        }
}

// ---------------------------------------------------------------------------
__global__ __launch_bounds__(256)
void combine_kernel(float* __restrict__ O) {
    const size_t N4 = (size_t)BS * SEQ * DK / 4;
    size_t i4 = (size_t)blockIdx.x * blockDim.x + threadIdx.x;
    if (i4 >= N4) return;
    const float4* P = (const float4*)g_part;
    float4 s = P[i4];
    #pragma unroll
    for (int sp = 1; sp < NS2; sp++) {
        float4 v = P[sp * N4 + i4];
        s.x += v.x; s.y += v.y; s.z += v.z; s.w += v.w;
    }
    ((float4*)O)[i4] = s;
}

// ---------------------------------------------------------------------------
extern "C" void kernel_launch(void* const* d_in, const int* in_sizes, int n_in,
                              void* d_out, int out_size) {
    const float* q = (const float*)d_in[0];
    const float* k = (const float*)d_in[1];
    const float* v = (const float*)d_in[2];
    float* out = (float*)d_out;

    cudaFuncSetAttribute(scores_hmma, cudaFuncAttributeMaxDynamicSharedMemorySize, SMEM_BYTES);
    cudaFuncSetAttribute(out_hmma,    cudaFuncAttributeMaxDynamicSharedMemorySize, SMEM_BYTES);

    zero_kernel<<<(BS * SEQ + 511) / 512, 512>>>();
    convert_qk<<<dim3(NT, 2, BS), 256>>>(q, k);
    scores_hmma<<<dim3(NT, NT, BS), 256, SMEM_BYTES>>>();
    recip_kernel<<<(BS * SEQ + 511) / 512, 512>>>();
    convert_v<<<dim3(NT, BS), 256>>>(v);
    out_hmma<<<dim3(NT, NS2, BS), 256, SMEM_BYTES>>>();
    combine_kernel<<<(BS * SEQ * DK / 4 + 255) / 256, 256>>>(out);
}

// round 13
// speedup vs baseline: 1.5284x; 1.5284x over previous
#include <cuda_runtime.h>
#include <cuda_bf16.h>
#include <cstdint>

#define BS 4
#define SEQ 4096
#define DK 128
#define SCALE 0.08838834764831843f   // 1/sqrt(128)
#define NT 32                        // 4096/128 tiles
#define NS2 4                        // split-K for output GEMM
#define SEG 4608                     // blob segment = 128 rows x 72 bf16 (144B rows)
#define TS  (4*SEG)                  // tile blob = [hi c0][hi c1][lo c0][lo c1]

// ---- scores pipeline stage (32-k subs): 4 parts x 128 rows x 80B
#define RS2 80
#define PART_BYTES 10240
#define P_AH 0
#define P_AL 10240
#define P_BH 20480
#define P_BL 30720
#define STAGE_BYTES 40960
#define SMEM_SCORES 81920            // 2 stages, occ 2

// ---- out pipeline chunk (64-k): 4 segs x 18432B (row stride 144)
#define C_AH 0
#define C_AL 18432
#define C_BH 36864
#define C_BL 55296
#define CHUNK_BYTES 73728
#define SMEM_OUT 147456              // 2 chunks, occ 1

// Blobs: exact padded images -> GEMM loads are raw async copies.
__device__ uint32_t g_Q[(size_t)BS*NT*TS];
__device__ uint32_t g_K[(size_t)BS*NT*TS];
__device__ uint32_t g_W[(size_t)BS*NT*TS];      // coef*V transposed [d][k]
__device__ uint32_t g_P[(size_t)BS*NT*NT*TS];   // ~300 MB
__device__ float g_colsum[BS*SEQ];
__device__ float g_part[(size_t)NS2*BS*SEQ*DK];

// ------------------------------------------------------------------ helpers
__device__ __forceinline__ uint32_t smem_u32(const void* p) {
    uint32_t a;
    asm("{ .reg .u64 t; cvta.to.shared.u64 t, %1; cvt.u32.u64 %0, t; }" : "=r"(a) : "l"(p));
    return a;
}
__device__ __forceinline__ void ldsm4(uint32_t* r, uint32_t addr) {
    asm volatile("ldmatrix.sync.aligned.m8n8.x4.shared.b16 {%0,%1,%2,%3}, [%4];"
                 : "=r"(r[0]), "=r"(r[1]), "=r"(r[2]), "=r"(r[3]) : "r"(addr));
}
// volatile: my grouped ordering IS the schedule.
__device__ __forceinline__ void mma16816(float* c, const uint32_t* a, uint32_t b0, uint32_t b1) {
    asm volatile("mma.sync.aligned.m16n8k16.row.col.f32.bf16.bf16.f32 "
                 "{%0,%1,%2,%3}, {%4,%5,%6,%7}, {%8,%9}, {%0,%1,%2,%3};"
                 : "+f"(c[0]), "+f"(c[1]), "+f"(c[2]), "+f"(c[3])
                 : "r"(a[0]), "r"(a[1]), "r"(a[2]), "r"(a[3]), "r"(b0), "r"(b1));
}
// Fast bf16 hi/lo split of a float pair: h = {y,x} bf16x2 via one cvt; lo via
// bit-derived hi floats + one more cvt. ~6 instr.
__device__ __forceinline__ void bsplit2(float x, float y, uint32_t& h, uint32_t& l) {
    asm("cvt.rn.bf16x2.f32 %0, %1, %2;" : "=r"(h) : "f"(y), "f"(x));
    float xh = __uint_as_float(h << 16);
    float yh = __uint_as_float(h & 0xFFFF0000u);
    float xl = x - xh, yl = y - yh;
    asm("cvt.rn.bf16x2.f32 %0, %1, %2;" : "=r"(l) : "f"(yl), "f"(xl));
}
__device__ __forceinline__ void cp16(uint32_t sdst, const void* gsrc) {
    asm volatile("cp.async.cg.shared.global [%0], [%1], 16;" :: "r"(sdst), "l"(gsrc) : "memory");
}
__device__ __forceinline__ void cp_commit() { asm volatile("cp.async.commit_group;" ::: "memory"); }
__device__ __forceinline__ void cp_wait0() { asm volatile("cp.async.wait_group 0;" ::: "memory"); }
__device__ __forceinline__ void cp_wait1() { asm volatile("cp.async.wait_group 1;" ::: "memory"); }

// ---- scores loader: one 32-k sub-chunk (4 parts x 128 rows x 64B) -> stage
__device__ __forceinline__ void issue_sub(uint32_t stage, const uint32_t* Ab, const uint32_t* Bb,
                                          int ch, int h, int tid) {
    const uint32_t* segs[4] = { Ab + ch * SEG, Ab + (2 + ch) * SEG,
                                Bb + ch * SEG, Bb + (2 + ch) * SEG };
    #pragma unroll
    for (int i = 0; i < 8; i++) {
        int t = tid + i * 256;
        int part = t >> 9;
        int w = t & 511, row = w >> 2, q = w & 3;
        const char* src = (const char*)segs[part] + row * 144 + h * 64 + q * 16;
        cp16(stage + part * PART_BYTES + row * RS2 + q * 16, src);
    }
    cp_commit();
}

// ---- out loader: one full 18432B segment -> chunk part (256 thr)
__device__ __forceinline__ void copy_seg_async(uint32_t sdst, const uint32_t* src, int tid) {
    #pragma unroll
    for (int i = 0; i < 5; i++) {
        int j = tid + i * 256;
        if (j < 1152) cp16(sdst + j * 16, (const char*)src + j * 16);
    }
}

// ---------------------------------------------------------------------------
// Grouped 3-pass bf16-split GEMM over a 32-k stage (scores; row stride 80).
// ---------------------------------------------------------------------------
__device__ __forceinline__ void mma_sub(uint32_t sbase, float acc[4][4][4],
                                        int warp_m, int warp_n, int lane) {
    int rIn  = (lane & 7) + ((lane >> 3) & 1) * 8;
    int kOff = (lane >> 4) * 16;
    int aRow0 = warp_m * 64 + rIn;
    int bRow0 = warp_n * 32 + rIn;

    #pragma unroll
    for (int s = 0; s < 2; s++) {
        uint32_t a[4][4], bh[2][4], bl[2][4];
        #pragma unroll
        for (int nj = 0; nj < 2; nj++) {
            ldsm4(bh[nj], sbase + P_BH + (bRow0 + nj * 16) * RS2 + kOff + s * 32);
            ldsm4(bl[nj], sbase + P_BL + (bRow0 + nj * 16) * RS2 + kOff + s * 32);
        }
        #pragma unroll
        for (int mi = 0; mi < 4; mi++)
            ldsm4(a[mi], sbase + P_AH + (aRow0 + mi * 16) * RS2 + kOff + s * 32);
        // group 1: A_hi x B_hi (16 independent accs)
        #pragma unroll
        for (int mi = 0; mi < 4; mi++)
            #pragma unroll
            for (int ng = 0; ng < 4; ng++) {
                int nj = ng >> 1, g = ng & 1;
                mma16816(acc[mi][ng], a[mi], bh[nj][g], bh[nj][g + 2]);
            }
        // group 2: A_hi x B_lo
        #pragma unroll
        for (int mi = 0; mi < 4; mi++)
            #pragma unroll
            for (int ng = 0; ng < 4; ng++) {
                int nj = ng >> 1, g = ng & 1;
                mma16816(acc[mi][ng], a[mi], bl[nj][g], bl[nj][g + 2]);
            }
        // group 3: A_lo x B_hi (a[] dead -> al reuses its registers)
        uint32_t al[4][4];
        #pragma unroll
        for (int mi = 0; mi < 4; mi++)
            ldsm4(al[mi], sbase + P_AL + (aRow0 + mi * 16) * RS2 + kOff + s * 32);
        #pragma unroll
        for (int mi = 0; mi < 4; mi++)
            #pragma unroll
            for (int ng = 0; ng < 4; ng++) {
                int nj = ng >> 1, g = ng & 1;
                mma16816(acc[mi][ng], al[mi], bh[nj][g], bh[nj][g + 2]);
            }
    }
}

// ---------------------------------------------------------------------------
// Grouped 3-pass GEMM over a 64-k chunk (out; row stride 144).
// ---------------------------------------------------------------------------
__device__ __forceinline__ void mma_chunk(uint32_t sb, float acc[4][4][4],
                                          int warp_m, int warp_n, int lane) {
    int rIn  = (lane & 7) + ((lane >> 3) & 1) * 8;
    int kOff = (lane >> 4) * 16;
    int aRow0 = warp_m * 64 + rIn;
    int bRow0 = warp_n * 32 + rIn;

    #pragma unroll
    for (int s = 0; s < 4; s++) {
        uint32_t a[4][4], bh[2][4], bl[2][4];
        #pragma unroll
        for (int nj = 0; nj < 2; nj++) {
            ldsm4(bh[nj], sb + C_BH + (bRow0 + nj * 16) * 144 + kOff + s * 32);
            ldsm4(bl[nj], sb + C_BL + (bRow0 + nj * 16) * 144 + kOff + s * 32);
        }
        #pragma unroll
        for (int mi = 0; mi < 4; mi++)
            ldsm4(a[mi], sb + C_AH + (aRow0 + mi * 16) * 144 + kOff + s * 32);
        #pragma unroll
        for (int mi = 0; mi < 4; mi++)
            #pragma unroll
            for (int ng = 0; ng < 4; ng++) {
                int nj = ng >> 1, g = ng & 1;
                mma16816(acc[mi][ng], a[mi], bh[nj][g], bh[nj][g + 2]);
            }
        #pragma unroll
        for (int mi = 0; mi < 4; mi++)
            #pragma unroll
            for (int ng = 0; ng < 4; ng++) {
                int nj = ng >> 1, g = ng & 1;
                mma16816(acc[mi][ng], a[mi], bl[nj][g], bl[nj][g + 2]);
            }
        uint32_t al[4][4];
        #pragma unroll
        for (int mi = 0; mi < 4; mi++)
            ldsm4(al[mi], sb + C_AL + (aRow0 + mi * 16) * 144 + kOff + s * 32);
        #pragma unroll
        for (int mi = 0; mi < 4; mi++)
            #pragma unroll
            for (int ng = 0; ng < 4; ng++) {
                int nj = ng >> 1, g = ng & 1;
                mma16816(acc[mi][ng], al[mi], bh[nj][g], bh[nj][g + 2]);
            }
    }
}

// ---------------------------------------------------------------- tiny kernels
__global__ void zero_kernel() {
    int i = blockIdx.x * blockDim.x + threadIdx.x;
    if (i < BS * SEQ) g_colsum[i] = 0.f;
}
__global__ void recip_kernel() {
    int i = blockIdx.x * blockDim.x + threadIdx.x;
    if (i < BS * SEQ) g_colsum[i] = 1.0f / g_colsum[i];
}

// ---------------------------------------------------------------------------
// Q/K f32 -> bf16 hi/lo padded blobs
// ---------------------------------------------------------------------------
__global__ __launch_bounds__(256)
void convert_qk(const float* __restrict__ Q, const float* __restrict__ K) {
    int tile = blockIdx.x, which = blockIdx.y, b = blockIdx.z;
    const float* src = (which ? K : Q) + ((size_t)b * SEQ + tile * 128) * DK;
    uint32_t* dst = (which ? g_K : g_Q) + (size_t)(b * NT + tile) * TS;

    for (int i = threadIdx.x; i < 2 * SEG; i += 256) {
        int ch = i / SEG, j = i % SEG;
        int row = j / 36, cp = j % 36;
        uint32_t h = 0, l = 0;
        if (cp < 32) {
            float2 v = *(const float2*)&src[row * DK + ch * 64 + cp * 2];
            bsplit2(v.x, v.y, h, l);
        }
        dst[ch * SEG + j] = h;
        dst[(2 + ch) * SEG + j] = l;
    }
}

// ---------------------------------------------------------------------------
// V f32 -> W blob: W[d][k] = coef_k * V[k][d], bf16 hi/lo, padded image.
// ---------------------------------------------------------------------------
__global__ __launch_bounds__(256)
void convert_v(const float* __restrict__ V) {
    int kb = blockIdx.x, b = blockIdx.y;
    const float* Vb = V + (size_t)b * SEQ * DK;
    const float* Cb = g_colsum + b * SEQ;
    uint32_t* dst = g_W + (size_t)(b * NT + kb) * TS;

    for (int i = threadIdx.x; i < 2 * SEG; i += 256) {
        int ch = i / SEG, j = i % SEG;
        int d = j / 36, kp = j % 36;
        uint32_t h = 0, l = 0;
        if (kp < 32) {
            int k = kb * 128 + ch * 64 + 2 * kp;
            float v0 = Vb[(size_t)k * DK + d]       * Cb[k];
            float v1 = Vb[(size_t)(k + 1) * DK + d] * Cb[k + 1];
            bsplit2(v0, v1, h, l);
        }
        dst[ch * SEG + j] = h;
        dst[(2 + ch) * SEG + j] = l;
    }
}

// ---------------------------------------------------------------------------
// Kernel 1: S = Q.K^T, 2-stage 32-k pipeline, grouped MMA; epilogue exp ->
// P blob + colsums via shuffle. occ 2.
// ---------------------------------------------------------------------------
__global__ __launch_bounds__(256, 2)
void scores_hmma() {
    extern __shared__ char smem[];
    uint32_t sb = smem_u32(smem);
    int tid = threadIdx.x, lane = tid & 31, wid = tid >> 5;
    int warp_m = wid >> 2, warp_n = wid & 3;
    int kt = blockIdx.x, qt = blockIdx.y, b = blockIdx.z;

    const uint32_t* Qb = g_Q + (size_t)(b * NT + qt) * TS;
    const uint32_t* Kb = g_K + (size_t)(b * NT + kt) * TS;

    float acc[4][4][4];
    #pragma unroll
    for (int i = 0; i < 4; i++)
        #pragma unroll
        for (int j = 0; j < 4; j++)
            #pragma unroll
            for (int c = 0; c < 4; c++) acc[i][j][c] = 0.f;

    issue_sub(sb, Qb, Kb, 0, 0, tid);
    issue_sub(sb + STAGE_BYTES, Qb, Kb, 0, 1, tid);

    for (int s = 0; s < 4; s++) {
        if (s < 3) cp_wait1(); else cp_wait0();
        __syncthreads();
        mma_sub(sb + (s & 1) * STAGE_BYTES, acc, warp_m, warp_n, lane);
        __syncthreads();
        if (s + 2 < 4)
            issue_sub(sb + (s & 1) * STAGE_BYTES, Qb, Kb, (s + 2) >> 1, (s + 2) & 1, tid);
    }

    // Epilogue: exp -> bf16 hi/lo staged as blob image; colsum partials in regs.
    float cs[4][2];
    #pragma unroll
    for (int ng = 0; ng < 4; ng++) { cs[ng][0] = 0.f; cs[ng][1] = 0.f; }

    #pragma unroll
    for (int mi = 0; mi < 4; mi++)
        #pragma unroll
        for (int ng = 0; ng < 4; ng++) {
            int R = warp_m * 64 + mi * 16 + (lane >> 2);
            int C = warp_n * 32 + ng * 8 + 2 * (lane & 3);
            int ch = C >> 6, cc = C & 63;
            #pragma unroll
            for (int rr = 0; rr < 2; rr++) {
                float p0 = __expf(acc[mi][ng][rr * 2]     * SCALE);
                float p1 = __expf(acc[mi][ng][rr * 2 + 1] * SCALE);
                cs[ng][0] += p0;
                cs[ng][1] += p1;
                uint32_t h, l;
                bsplit2(p0, p1, h, l);
                int off = ch * 18432 + (R + rr * 8) * 144 + cc * 2;
                *(uint32_t*)(smem + off)         = h;
                *(uint32_t*)(smem + 36864 + off) = l;
            }
        }

    // Shuffle-reduce colsums over the 8 lanes sharing a column, then atomic.
    #pragma unroll
    for (int ng = 0; ng < 4; ng++)
        #pragma unroll
        for (int c = 0; c < 2; c++) {
            float v = cs[ng][c];
            v += __shfl_xor_sync(0xFFFFFFFF, v, 4);
            v += __shfl_xor_sync(0xFFFFFFFF, v, 8);
            v += __shfl_xor_sync(0xFFFFFFFF, v, 16);
            if ((lane >> 2) == 0) {
                int col = warp_n * 32 + ng * 8 + 2 * (lane & 3) + c;
                atomicAdd(&g_colsum[b * SEQ + kt * 128 + col], v);
            }
        }
    __syncthreads();

    // Dump the staged blob (coalesced)
    {
        size_t blob = ((size_t)(b * NT + qt) * NT + kt) * TS;
        uint4* d4 = (uint4*)(g_P + blob);
        const uint4* s4 = (const uint4*)smem;
        #pragma unroll
        for (int i = 0; i < 18; i++) d4[tid + i * 256] = s4[tid + i * 256];
    }
}

// ---------------------------------------------------------------------------
// Kernel 2: partial[split] = sum_k P~[q,k] * W~[k,d] -> g_part
// occ 1, 2-stage 64-k chunk pipeline, grouped MMA. 16 steps.
// ---------------------------------------------------------------------------
__global__ __launch_bounds__(256, 1)
void out_hmma() {
    extern __shared__ char smem[];
    uint32_t sb = smem_u32(smem);
    int tid = threadIdx.x, lane = tid & 31, wid = tid >> 5;
    int warp_m = wid >> 2, warp_n = wid & 3;
    int qt = blockIdx.x, split = blockIdx.y, b = blockIdx.z;

    float acc[4][4][4];
    #pragma unroll
    for (int i = 0; i < 4; i++)
        #pragma unroll
        for (int j = 0; j < 4; j++)
            #pragma unroll
            for (int c = 0; c < 4; c++) acc[i][j][c] = 0.f;

    auto issue = [&](int step, int bi) {
        int kb = split * (NT / NS2) + (step >> 1);
        int h  = step & 1;
        const uint32_t* Pb = g_P + ((size_t)(b * NT + qt) * NT + kb) * TS;
        const uint32_t* Wb = g_W + (size_t)(b * NT + kb) * TS;
        uint32_t base = sb + bi * CHUNK_BYTES;
        copy_seg_async(base + C_AH, Pb + h * SEG, tid);
        copy_seg_async(base + C_AL, Pb + (2 + h) * SEG, tid);
        copy_seg_async(base + C_BH, Wb + h * SEG, tid);
        copy_seg_async(base + C_BL, Wb + (2 + h) * SEG, tid);
        cp_commit();
    };

    issue(0, 0);
    issue(1, 1);

    const int NSTEP = 2 * (NT / NS2);   // 16
    for (int s = 0; s < NSTEP; s++) {
        if (s < NSTEP - 1) cp_wait1(); else cp_wait0();
        __syncthreads();
        mma_chunk(sb + (s & 1) * CHUNK_BYTES, acc, warp_m, warp_n, lane);
        __syncthreads();
        if (s + 2 < NSTEP) issue(s + 2, s & 1);
    }

    // Epilogue: f32 partial writes (coalesced float2)
    float* Pb = g_part + ((size_t)(split * BS + b) * SEQ + qt * 128) * DK;
    #pragma unroll
    for (int mi = 0; mi < 4; mi++)
        #pragma unroll
        for (int ng = 0; ng < 4; ng++) {
            int R = warp_m * 64 + mi * 16 + (lane >> 2);
            int C = warp_n * 32 + ng * 8 + 2 * (lane & 3);
            float2 v0 = make_float2(acc[mi][ng][0], acc[mi][ng][1]);
            float2 v1 = make_float2(acc[mi][ng][2], acc[mi][ng][3]);
            *(float2*)&Pb[(size_t)R * DK + C]       = v0;
            *(float2*)&Pb[(size_t)(R + 8) * DK + C] = v1;
        }
}

// ---------------------------------------------------------------------------
__global__ __launch_bounds__(256)
void combine_kernel(float* __restrict__ O) {
    const size_t N4 = (size_t)BS * SEQ * DK / 4;
    size_t i4 = (size_t)blockIdx.x * blockDim.x + threadIdx.x;
    if (i4 >= N4) return;
    const float4* P = (const float4*)g_part;
    float4 s = P[i4];
    #pragma unroll
    for (int sp = 1; sp < NS2; sp++) {
        float4 v = P[sp * N4 + i4];
        s.x += v.x; s.y += v.y; s.z += v.z; s.w += v.w;
    }
    ((float4*)O)[i4] = s;
}

// ---------------------------------------------------------------------------
extern "C" void kernel_launch(void* const* d_in, const int* in_sizes, int n_in,
                              void* d_out, int out_size) {
    const float* q = (const float*)d_in[0];
    const float* k = (const float*)d_in[1];
    const float* v = (const float*)d_in[2];
    float* out = (float*)d_out;

    cudaFuncSetAttribute(scores_hmma, cudaFuncAttributeMaxDynamicSharedMemorySize, SMEM_SCORES);
    cudaFuncSetAttribute(out_hmma,    cudaFuncAttributeMaxDynamicSharedMemorySize, SMEM_OUT);

    zero_kernel<<<(BS * SEQ + 511) / 512, 512>>>();
    convert_qk<<<dim3(NT, 2, BS), 256>>>(q, k);
    scores_hmma<<<dim3(NT, NT, BS), 256, SMEM_SCORES>>>();
    recip_kernel<<<(BS * SEQ + 511) / 512, 512>>>();
    convert_v<<<dim3(NT, BS), 256>>>(v);
    out_hmma<<<dim3(NT, NS2, BS), 256, SMEM_OUT>>>();
    combine_kernel<<<(BS * SEQ * DK / 4 + 255) / 256, 256>>>(out);
}

// round 14
// speedup vs baseline: 1.5652x; 1.0241x over previous
#include <cuda_runtime.h>
#include <cuda_bf16.h>
#include <cstdint>

#define BS 4
#define SEQ 4096
#define DK 128
#define SCALE 0.08838834764831843f   // 1/sqrt(128)
#define NT 32                        // 4096/128 tiles
#define NS2 8                        // split-K for output GEMM
#define SEG 4608                     // Q/K/W blob segment = 128 rows x 72 u32 (144B rows)
#define TS  (4*SEG)                  // Q/K/W tile blob = [hi c0][hi c1][lo c0][lo c1]

// ---- scores pipeline stage (32-k subs): 4 parts x 128 rows x 80B
#define RS2 80
#define PART_BYTES 10240
#define P_AH 0
#define P_AL 10240
#define P_BH 20480
#define P_BL 30720
#define STAGE_BYTES 40960
#define SMEM_SCORES 81920            // 2 stages, occ 2

// ---- out: smem holds only W; one 64-k chunk = hi seg + lo seg
#define OC_BH 0
#define OC_BL 18432
#define OCHUNK 36864
#define SMEM_OUT 73728               // 2 chunks, occ 2

// ---- fragment-native P blob: per (b,qt,kt) tile:
//   [hl:2][q16:8][k16:8][lane:32] x 16B  -> 16384 u32 = 64KB/tile
#define TSP 16384

__device__ uint32_t g_Q[(size_t)BS*NT*TS];
__device__ uint32_t g_K[(size_t)BS*NT*TS];
__device__ uint32_t g_W[(size_t)BS*NT*TS];        // coef*V transposed [d][k]
__device__ uint32_t g_P2[(size_t)BS*NT*NT*TSP];   // 256 MB fragment-native P
__device__ float g_colsum[BS*SEQ];
__device__ float g_part[(size_t)NS2*BS*SEQ*DK];

// ------------------------------------------------------------------ helpers
__device__ __forceinline__ uint32_t smem_u32(const void* p) {
    uint32_t a;
    asm("{ .reg .u64 t; cvta.to.shared.u64 t, %1; cvt.u32.u64 %0, t; }" : "=r"(a) : "l"(p));
    return a;
}
__device__ __forceinline__ void ldsm4(uint32_t* r, uint32_t addr) {
    asm volatile("ldmatrix.sync.aligned.m8n8.x4.shared.b16 {%0,%1,%2,%3}, [%4];"
                 : "=r"(r[0]), "=r"(r[1]), "=r"(r[2]), "=r"(r[3]) : "r"(addr));
}
__device__ __forceinline__ void mma16816(float* c, const uint32_t* a, uint32_t b0, uint32_t b1) {
    asm volatile("mma.sync.aligned.m16n8k16.row.col.f32.bf16.bf16.f32 "
                 "{%0,%1,%2,%3}, {%4,%5,%6,%7}, {%8,%9}, {%0,%1,%2,%3};"
                 : "+f"(c[0]), "+f"(c[1]), "+f"(c[2]), "+f"(c[3])
                 : "r"(a[0]), "r"(a[1]), "r"(a[2]), "r"(a[3]), "r"(b0), "r"(b1));
}
__device__ __forceinline__ void bsplit2(float x, float y, uint32_t& h, uint32_t& l) {
    asm("cvt.rn.bf16x2.f32 %0, %1, %2;" : "=r"(h) : "f"(y), "f"(x));
    float xh = __uint_as_float(h << 16);
    float yh = __uint_as_float(h & 0xFFFF0000u);
    float xl = x - xh, yl = y - yh;
    asm("cvt.rn.bf16x2.f32 %0, %1, %2;" : "=r"(l) : "f"(yl), "f"(xl));
}
__device__ __forceinline__ void cp16(uint32_t sdst, const void* gsrc) {
    asm volatile("cp.async.cg.shared.global [%0], [%1], 16;" :: "r"(sdst), "l"(gsrc) : "memory");
}
__device__ __forceinline__ void cp_commit() { asm volatile("cp.async.commit_group;" ::: "memory"); }
__device__ __forceinline__ void cp_wait0() { asm volatile("cp.async.wait_group 0;" ::: "memory"); }
__device__ __forceinline__ void cp_wait1() { asm volatile("cp.async.wait_group 1;" ::: "memory"); }

// ---- scores loader: one 32-k sub-chunk (4 parts x 128 rows x 64B) -> stage
__device__ __forceinline__ void issue_sub(uint32_t stage, const uint32_t* Ab, const uint32_t* Bb,
                                          int ch, int h, int tid) {
    const uint32_t* segs[4] = { Ab + ch * SEG, Ab + (2 + ch) * SEG,
                                Bb + ch * SEG, Bb + (2 + ch) * SEG };
    #pragma unroll
    for (int i = 0; i < 8; i++) {
        int t = tid + i * 256;
        int part = t >> 9;
        int w = t & 511, row = w >> 2, q = w & 3;
        const char* src = (const char*)segs[part] + row * 144 + h * 64 + q * 16;
        cp16(stage + part * PART_BYTES + row * RS2 + q * 16, src);
    }
    cp_commit();
}
// ---- out loader: one full 18432B W segment -> chunk part
__device__ __forceinline__ void copy_seg_async(uint32_t sdst, const uint32_t* src, int tid) {
    #pragma unroll
    for (int i = 0; i < 5; i++) {
        int j = tid + i * 256;
        if (j < 1152) cp16(sdst + j * 16, (const char*)src + j * 16);
    }
}

// ---------------------------------------------------------------------------
// Champion 3-pass bf16-split GEMM over a 32-k stage (scores; row stride 80).
// ---------------------------------------------------------------------------
__device__ __forceinline__ void mma_sub(uint32_t sbase, float acc[4][4][4],
                                        int warp_m, int warp_n, int lane) {
    int rIn  = (lane & 7) + ((lane >> 3) & 1) * 8;
    int kOff = (lane >> 4) * 16;
    int aRow0 = warp_m * 64 + rIn;
    int bRow0 = warp_n * 32 + rIn;

    // pass 1+2: A_hi x (B_hi, B_lo)
    #pragma unroll
    for (int s = 0; s < 2; s++) {
        uint32_t a[4][4], bh[2][4], bl[2][4];
        #pragma unroll
        for (int mi = 0; mi < 4; mi++)
            ldsm4(a[mi], sbase + P_AH + (aRow0 + mi * 16) * RS2 + kOff + s * 32);
        #pragma unroll
        for (int nj = 0; nj < 2; nj++) {
            ldsm4(bh[nj], sbase + P_BH + (bRow0 + nj * 16) * RS2 + kOff + s * 32);
            ldsm4(bl[nj], sbase + P_BL + (bRow0 + nj * 16) * RS2 + kOff + s * 32);
        }
        #pragma unroll
        for (int mi = 0; mi < 4; mi++)
            #pragma unroll
            for (int ng = 0; ng < 4; ng++) {
                int nj = ng >> 1, g = ng & 1;
                mma16816(acc[mi][ng], a[mi], bh[nj][g], bh[nj][g + 2]);
                mma16816(acc[mi][ng], a[mi], bl[nj][g], bl[nj][g + 2]);
            }
    }
    // pass 3: A_lo x B_hi
    #pragma unroll
    for (int s = 0; s < 2; s++) {
        uint32_t a[4][4], bh[2][4];
        #pragma unroll
        for (int mi = 0; mi < 4; mi++)
            ldsm4(a[mi], sbase + P_AL + (aRow0 + mi * 16) * RS2 + kOff + s * 32);
        #pragma unroll
        for (int nj = 0; nj < 2; nj++)
            ldsm4(bh[nj], sbase + P_BH + (bRow0 + nj * 16) * RS2 + kOff + s * 32);
        #pragma unroll
        for (int mi = 0; mi < 4; mi++)
            #pragma unroll
            for (int ng = 0; ng < 4; ng++) {
                int nj = ng >> 1, g = ng & 1;
                mma16816(acc[mi][ng], a[mi], bh[nj][g], bh[nj][g + 2]);
            }
    }
}

// ---------------------------------------------------------------- tiny kernels
__global__ void zero_kernel() {
    int i = blockIdx.x * blockDim.x + threadIdx.x;
    if (i < BS * SEQ) g_colsum[i] = 0.f;
}
__global__ void recip_kernel() {
    int i = blockIdx.x * blockDim.x + threadIdx.x;
    if (i < BS * SEQ) g_colsum[i] = 1.0f / g_colsum[i];
}

// ---------------------------------------------------------------------------
// Q/K f32 -> bf16 hi/lo padded blobs
// ---------------------------------------------------------------------------
__global__ __launch_bounds__(256)
void convert_qk(const float* __restrict__ Q, const float* __restrict__ K) {
    int tile = blockIdx.x, which = blockIdx.y, b = blockIdx.z;
    const float* src = (which ? K : Q) + ((size_t)b * SEQ + tile * 128) * DK;
    uint32_t* dst = (which ? g_K : g_Q) + (size_t)(b * NT + tile) * TS;

    for (int i = threadIdx.x; i < 2 * SEG; i += 256) {
        int ch = i / SEG, j = i % SEG;
        int row = j / 36, cp = j % 36;
        uint32_t h = 0, l = 0;
        if (cp < 32) {
            float2 v = *(const float2*)&src[row * DK + ch * 64 + cp * 2];
            bsplit2(v.x, v.y, h, l);
        }
        dst[ch * SEG + j] = h;
        dst[(2 + ch) * SEG + j] = l;
    }
}

// ---------------------------------------------------------------------------
// V f32 -> W blob: W[d][k] = coef_k * V[k][d], bf16 hi/lo, padded image.
// ---------------------------------------------------------------------------
__global__ __launch_bounds__(256)
void convert_v(const float* __restrict__ V) {
    int kb = blockIdx.x, b = blockIdx.y;
    const float* Vb = V + (size_t)b * SEQ * DK;
    const float* Cb = g_colsum + b * SEQ;
    uint32_t* dst = g_W + (size_t)(b * NT + kb) * TS;

    for (int i = threadIdx.x; i < 2 * SEG; i += 256) {
        int ch = i / SEG, j = i % SEG;
        int d = j / 36, kp = j % 36;
        uint32_t h = 0, l = 0;
        if (kp < 32) {
            int k = kb * 128 + ch * 64 + 2 * kp;
            float v0 = Vb[(size_t)k * DK + d]       * Cb[k];
            float v1 = Vb[(size_t)(k + 1) * DK + d] * Cb[k + 1];
            bsplit2(v0, v1, h, l);
        }
        dst[ch * SEG + j] = h;
        dst[(2 + ch) * SEG + j] = l;
    }
}

// ---------------------------------------------------------------------------
// Kernel 1: S = Q.K^T (champion mainloop); epilogue exp -> fragment-native
// P blob via coalesced STG.128 (no smem staging, no post-loop barrier).
// ---------------------------------------------------------------------------
__global__ __launch_bounds__(256, 2)
void scores_hmma() {
    extern __shared__ char smem[];
    uint32_t sb = smem_u32(smem);
    int tid = threadIdx.x, lane = tid & 31, wid = tid >> 5;
    int warp_m = wid >> 2, warp_n = wid & 3;
    int kt = blockIdx.x, qt = blockIdx.y, b = blockIdx.z;

    const uint32_t* Qb = g_Q + (size_t)(b * NT + qt) * TS;
    const uint32_t* Kb = g_K + (size_t)(b * NT + kt) * TS;

    float acc[4][4][4];
    #pragma unroll
    for (int i = 0; i < 4; i++)
        #pragma unroll
        for (int j = 0; j < 4; j++)
            #pragma unroll
            for (int c = 0; c < 4; c++) acc[i][j][c] = 0.f;

    issue_sub(sb, Qb, Kb, 0, 0, tid);
    issue_sub(sb + STAGE_BYTES, Qb, Kb, 0, 1, tid);

    for (int s = 0; s < 4; s++) {
        if (s < 3) cp_wait1(); else cp_wait0();
        __syncthreads();
        mma_sub(sb + (s & 1) * STAGE_BYTES, acc, warp_m, warp_n, lane);
        __syncthreads();
        if (s + 2 < 4)
            issue_sub(sb + (s & 1) * STAGE_BYTES, Qb, Kb, (s + 2) >> 1, (s + 2) & 1, tid);
    }

    // Epilogue: exp -> bf16 hi/lo fragments -> direct coalesced global stores.
    uint32_t* Pt = g_P2 + ((size_t)(b * NT + qt) * NT + kt) * TSP;
    float cs[4][2];
    #pragma unroll
    for (int ng = 0; ng < 4; ng++) { cs[ng][0] = 0.f; cs[ng][1] = 0.f; }

    #pragma unroll
    for (int mi = 0; mi < 4; mi++) {
        uint32_t hh[4][2], ll[4][2];
        #pragma unroll
        for (int ng = 0; ng < 4; ng++)
            #pragma unroll
            for (int rr = 0; rr < 2; rr++) {
                float p0 = __expf(acc[mi][ng][rr * 2]     * SCALE);
                float p1 = __expf(acc[mi][ng][rr * 2 + 1] * SCALE);
                cs[ng][0] += p0;
                cs[ng][1] += p1;
                bsplit2(p0, p1, hh[ng][rr], ll[ng][rr]);
            }
        int q16 = warp_m * 4 + mi;
        #pragma unroll
        for (int j = 0; j < 2; j++) {
            int k16 = warp_n * 2 + j;
            uint32_t off = (uint32_t)(q16 * 8 + k16) * 128 + lane * 4;
            *(uint4*)(Pt + off) =
                make_uint4(hh[2*j][0], hh[2*j][1], hh[2*j+1][0], hh[2*j+1][1]);
            *(uint4*)(Pt + 8192 + off) =
                make_uint4(ll[2*j][0], ll[2*j][1], ll[2*j+1][0], ll[2*j+1][1]);
        }
    }

    // Shuffle-reduce colsums over the 8 lanes sharing a column, then atomic.
    #pragma unroll
    for (int ng = 0; ng < 4; ng++)
        #pragma unroll
        for (int c = 0; c < 2; c++) {
            float v = cs[ng][c];
            v += __shfl_xor_sync(0xFFFFFFFF, v, 4);
            v += __shfl_xor_sync(0xFFFFFFFF, v, 8);
            v += __shfl_xor_sync(0xFFFFFFFF, v, 16);
            if ((lane >> 2) == 0) {
                int col = warp_n * 32 + ng * 8 + 2 * (lane & 3) + c;
                atomicAdd(&g_colsum[b * SEQ + kt * 128 + col], v);
            }
        }
}

// ---------------------------------------------------------------------------
// Kernel 2: partial[split] = sum_k P~[q,k] * W~[k,d] -> g_part
// A-fragments loaded straight from g_P2 via LDG.128; only W pipelined in smem.
// occ 2, 2-chunk (64-k) double buffer, 8 steps.
// ---------------------------------------------------------------------------
__global__ __launch_bounds__(256, 2)
void out_hmma() {
    extern __shared__ char smem[];
    uint32_t sb = smem_u32(smem);
    int tid = threadIdx.x, lane = tid & 31, wid = tid >> 5;
    int warp_m = wid >> 2, warp_n = wid & 3;
    int qt = blockIdx.x, split = blockIdx.y, b = blockIdx.z;

    float acc[4][4][4];
    #pragma unroll
    for (int i = 0; i < 4; i++)
        #pragma unroll
        for (int j = 0; j < 4; j++)
            #pragma unroll
            for (int c = 0; c < 4; c++) acc[i][j][c] = 0.f;

    auto issue = [&](int step, int bi) {
        int kb = split * (NT / NS2) + (step >> 1);
        int h  = step & 1;
        const uint32_t* Wb = g_W + (size_t)(b * NT + kb) * TS;
        uint32_t base = sb + bi * OCHUNK;
        copy_seg_async(base + OC_BH, Wb + h * SEG, tid);
        copy_seg_async(base + OC_BL, Wb + (2 + h) * SEG, tid);
        cp_commit();
    };

    issue(0, 0);
    issue(1, 1);

    int rIn  = (lane & 7) + ((lane >> 3) & 1) * 8;
    int kOff = (lane >> 4) * 16;
    int bRow0 = warp_n * 32 + rIn;

    const int NSTEP = 2 * (NT / NS2);   // 8
    for (int s2 = 0; s2 < NSTEP; s2++) {
        if (s2 < NSTEP - 1) cp_wait1(); else cp_wait0();
        __syncthreads();
        uint32_t stage = sb + (s2 & 1) * OCHUNK;
        int kb = split * (NT / NS2) + (s2 >> 1);
        int h  = s2 & 1;
        const uint32_t* pA = g_P2 + ((size_t)(b * NT + qt) * NT + kb) * TSP
                           + warp_m * 4096 + lane * 4;

        // pass 1+2 over the 64-k chunk
        #pragma unroll
        for (int s = 0; s < 4; s++) {
            int k16 = h * 4 + s;
            uint32_t a[4][4], bh[2][4], bl[2][4];
            #pragma unroll
            for (int mi = 0; mi < 4; mi++)
                *(uint4*)a[mi] = *(const uint4*)(pA + (uint32_t)(mi * 8 + k16) * 128);
            #pragma unroll
            for (int nj = 0; nj < 2; nj++) {
                ldsm4(bh[nj], stage + OC_BH + (bRow0 + nj * 16) * 144 + kOff + s * 32);
                ldsm4(bl[nj], stage + OC_BL + (bRow0 + nj * 16) * 144 + kOff + s * 32);
            }
            #pragma unroll
            for (int mi = 0; mi < 4; mi++)
                #pragma unroll
                for (int ng = 0; ng < 4; ng++) {
                    int nj = ng >> 1, g = ng & 1;
                    mma16816(acc[mi][ng], a[mi], bh[nj][g], bh[nj][g + 2]);
                    mma16816(acc[mi][ng], a[mi], bl[nj][g], bl[nj][g + 2]);
                }
        }
        // pass 3: A_lo x B_hi
        #pragma unroll
        for (int s = 0; s < 4; s++) {
            int k16 = h * 4 + s;
            uint32_t a[4][4], bh[2][4];
            #pragma unroll
            for (int mi = 0; mi < 4; mi++)
                *(uint4*)a[mi] = *(const uint4*)(pA + 8192 + (uint32_t)(mi * 8 + k16) * 128);
            #pragma unroll
            for (int nj = 0; nj < 2; nj++)
                ldsm4(bh[nj], stage + OC_BH + (bRow0 + nj * 16) * 144 + kOff + s * 32);
            #pragma unroll
            for (int mi = 0; mi < 4; mi++)
                #pragma unroll
                for (int ng = 0; ng < 4; ng++) {
                    int nj = ng >> 1, g = ng & 1;
                    mma16816(acc[mi][ng], a[mi], bh[nj][g], bh[nj][g + 2]);
                }
        }
        __syncthreads();
        if (s2 + 2 < NSTEP) issue(s2 + 2, s2 & 1);
    }

    // Epilogue: f32 partial writes (coalesced float2)
    float* Pb = g_part + ((size_t)(split * BS + b) * SEQ + qt * 128) * DK;
    #pragma unroll
    for (int mi = 0; mi < 4; mi++)
        #pragma unroll
        for (int ng = 0; ng < 4; ng++) {
            int R = warp_m * 64 + mi * 16 + (lane >> 2);
            int C = warp_n * 32 + ng * 8 + 2 * (lane & 3);
            float2 v0 = make_float2(acc[mi][ng][0], acc[mi][ng][1]);
            float2 v1 = make_float2(acc[mi][ng][2], acc[mi][ng][3]);
            *(float2*)&Pb[(size_t)R * DK + C]       = v0;
            *(float2*)&Pb[(size_t)(R + 8) * DK + C] = v1;
        }
}

// ---------------------------------------------------------------------------
__global__ __launch_bounds__(256)
void combine_kernel(float* __restrict__ O) {
    const size_t N4 = (size_t)BS * SEQ * DK / 4;
    size_t i4 = (size_t)blockIdx.x * blockDim.x + threadIdx.x;
    if (i4 >= N4) return;
    const float4* P = (const float4*)g_part;
    float4 s = P[i4];
    #pragma unroll
    for (int sp = 1; sp < NS2; sp++) {
        float4 v = P[sp * N4 + i4];
        s.x += v.x; s.y += v.y; s.z += v.z; s.w += v.w;
    }
    ((float4*)O)[i4] = s;
}

// ---------------------------------------------------------------------------
extern "C" void kernel_launch(void* const* d_in, const int* in_sizes, int n_in,
                              void* d_out, int out_size) {
    const float* q = (const float*)d_in[0];
    const float* k = (const float*)d_in[1];
    const float* v = (const float*)d_in[2];
    float* out = (float*)d_out;

    cudaFuncSetAttribute(scores_hmma, cudaFuncAttributeMaxDynamicSharedMemorySize, SMEM_SCORES);
    cudaFuncSetAttribute(out_hmma,    cudaFuncAttributeMaxDynamicSharedMemorySize, SMEM_OUT);

    zero_kernel<<<(BS * SEQ + 511) / 512, 512>>>();
    convert_qk<<<dim3(NT, 2, BS), 256>>>(q, k);
    scores_hmma<<<dim3(NT, NT, BS), 256, SMEM_SCORES>>>();
    recip_kernel<<<(BS * SEQ + 511) / 512, 512>>>();
    convert_v<<<dim3(NT, BS), 256>>>(v);
    out_hmma<<<dim3(NT, NS2, BS), 256, SMEM_OUT>>>();
    combine_kernel<<<(BS * SEQ * DK / 4 + 255) / 256, 256>>>(out);
}

// round 15
// speedup vs baseline: 2.0225x; 1.2922x over previous
#include <cuda_runtime.h>
#include <cuda_bf16.h>
#include <cuda_fp16.h>
#include <cstdint>

#define BS 4
#define SEQ 4096
#define DK 128
#define SCALE 0.08838834764831843f   // 1/sqrt(128)
#define NT 32                        // 4096/128 tiles
#define NS2 8                        // split-K for output GEMM
#define SEG 4608                     // blob segment = 128 rows x 72 u32 (144B rows)
#define TS  (4*SEG)                  // Q/K/W tile blob = [hi c0][hi c1][lo c0][lo c1]
#define TSP2 (2*SEG)                 // fp16 P tile blob = [c0][c1], [q][k] rows of 144B
#define WSCALE 4096.0f
#define INV_WSCALE (1.0f/4096.0f)

// ---- scores pipeline stage (32-k subs): 4 parts x 128 rows x 80B
#define RS2 80
#define PART_BYTES 10240
#define P_AH 0
#define P_AL 10240
#define P_BH 20480
#define P_BL 30720
#define STAGE_BYTES 40960
#define SMEM_SCORES 81920            // 2 stages, occ 2 (epilogue stages 36864B in-place)

// ---- out chunk (64-k): [A fp16][W_hi fp16][W_lo fp16] segments
#define OC_A  0
#define OC_BH 18432
#define OC_BL 36864
#define OCHUNK 55296
#define SMEM_OUT 110592              // 2 chunks, occ 2

__device__ uint32_t g_Q[(size_t)BS*NT*TS];
__device__ uint32_t g_K[(size_t)BS*NT*TS];
__device__ uint32_t g_W[(size_t)BS*NT*TS];        // fp16 hi/lo of WSCALE*coef*V^T [d][k]
__device__ uint32_t g_P[(size_t)BS*NT*NT*TSP2];   // 151 MB fp16 P
__device__ float g_colsum[BS*SEQ];
__device__ float g_part[(size_t)NS2*BS*SEQ*DK];

// ------------------------------------------------------------------ helpers
__device__ __forceinline__ uint32_t smem_u32(const void* p) {
    uint32_t a;
    asm("{ .reg .u64 t; cvta.to.shared.u64 t, %1; cvt.u32.u64 %0, t; }" : "=r"(a) : "l"(p));
    return a;
}
__device__ __forceinline__ void ldsm4(uint32_t* r, uint32_t addr) {
    asm volatile("ldmatrix.sync.aligned.m8n8.x4.shared.b16 {%0,%1,%2,%3}, [%4];"
                 : "=r"(r[0]), "=r"(r[1]), "=r"(r[2]), "=r"(r[3]) : "r"(addr));
}
__device__ __forceinline__ void mma_bf16(float* c, const uint32_t* a, uint32_t b0, uint32_t b1) {
    asm volatile("mma.sync.aligned.m16n8k16.row.col.f32.bf16.bf16.f32 "
                 "{%0,%1,%2,%3}, {%4,%5,%6,%7}, {%8,%9}, {%0,%1,%2,%3};"
                 : "+f"(c[0]), "+f"(c[1]), "+f"(c[2]), "+f"(c[3])
                 : "r"(a[0]), "r"(a[1]), "r"(a[2]), "r"(a[3]), "r"(b0), "r"(b1));
}
__device__ __forceinline__ void mma_f16(float* c, const uint32_t* a, uint32_t b0, uint32_t b1) {
    asm volatile("mma.sync.aligned.m16n8k16.row.col.f32.f16.f16.f32 "
                 "{%0,%1,%2,%3}, {%4,%5,%6,%7}, {%8,%9}, {%0,%1,%2,%3};"
                 : "+f"(c[0]), "+f"(c[1]), "+f"(c[2]), "+f"(c[3])
                 : "r"(a[0]), "r"(a[1]), "r"(a[2]), "r"(a[3]), "r"(b0), "r"(b1));
}
// bf16 hi/lo split (Q/K)
__device__ __forceinline__ void bsplit2(float x, float y, uint32_t& h, uint32_t& l) {
    asm("cvt.rn.bf16x2.f32 %0, %1, %2;" : "=r"(h) : "f"(y), "f"(x));
    float xh = __uint_as_float(h << 16);
    float yh = __uint_as_float(h & 0xFFFF0000u);
    float xl = x - xh, yl = y - yh;
    asm("cvt.rn.bf16x2.f32 %0, %1, %2;" : "=r"(l) : "f"(yl), "f"(xl));
}
// fp16 hi/lo split (W)
__device__ __forceinline__ void hsplit2(float x, float y, uint32_t& h, uint32_t& l) {
    asm("cvt.rn.f16x2.f32 %0, %1, %2;" : "=r"(h) : "f"(y), "f"(x));
    float xh, yh;
    asm("{ .reg .b16 lo, hi; mov.b32 {lo, hi}, %2;\n\t"
        "cvt.f32.f16 %0, lo; cvt.f32.f16 %1, hi; }" : "=f"(xh), "=f"(yh) : "r"(h));
    float xl = x - xh, yl = y - yh;
    asm("cvt.rn.f16x2.f32 %0, %1, %2;" : "=r"(l) : "f"(yl), "f"(xl));
}
__device__ __forceinline__ uint32_t f16pack(float x, float y) {
    uint32_t r;
    asm("cvt.rn.f16x2.f32 %0, %1, %2;" : "=r"(r) : "f"(y), "f"(x));
    return r;
}
__device__ __forceinline__ void cp16(uint32_t sdst, const void* gsrc) {
    asm volatile("cp.async.cg.shared.global [%0], [%1], 16;" :: "r"(sdst), "l"(gsrc) : "memory");
}
__device__ __forceinline__ void cp_commit() { asm volatile("cp.async.commit_group;" ::: "memory"); }
__device__ __forceinline__ void cp_wait0() { asm volatile("cp.async.wait_group 0;" ::: "memory"); }
__device__ __forceinline__ void cp_wait1() { asm volatile("cp.async.wait_group 1;" ::: "memory"); }

// ---- scores loader: one 32-k sub-chunk (4 parts x 128 rows x 64B) -> stage
__device__ __forceinline__ void issue_sub(uint32_t stage, const uint32_t* Ab, const uint32_t* Bb,
                                          int ch, int h, int tid) {
    const uint32_t* segs[4] = { Ab + ch * SEG, Ab + (2 + ch) * SEG,
                                Bb + ch * SEG, Bb + (2 + ch) * SEG };
    #pragma unroll
    for (int i = 0; i < 8; i++) {
        int t = tid + i * 256;
        int part = t >> 9;
        int w = t & 511, row = w >> 2, q = w & 3;
        const char* src = (const char*)segs[part] + row * 144 + h * 64 + q * 16;
        cp16(stage + part * PART_BYTES + row * RS2 + q * 16, src);
    }
    cp_commit();
}
// ---- one full 18432B segment -> smem
__device__ __forceinline__ void copy_seg_async(uint32_t sdst, const uint32_t* src, int tid) {
    #pragma unroll
    for (int i = 0; i < 5; i++) {
        int j = tid + i * 256;
        if (j < 1152) cp16(sdst + j * 16, (const char*)src + j * 16);
    }
}

// ---------------------------------------------------------------------------
// Champion 3-pass bf16-split GEMM over a 32-k stage (scores; row stride 80).
// ---------------------------------------------------------------------------
__device__ __forceinline__ void mma_sub(uint32_t sbase, float acc[4][4][4],
                                        int warp_m, int warp_n, int lane) {
    int rIn  = (lane & 7) + ((lane >> 3) & 1) * 8;
    int kOff = (lane >> 4) * 16;
    int aRow0 = warp_m * 64 + rIn;
    int bRow0 = warp_n * 32 + rIn;

    #pragma unroll
    for (int s = 0; s < 2; s++) {
        uint32_t a[4][4], bh[2][4], bl[2][4];
        #pragma unroll
        for (int mi = 0; mi < 4; mi++)
            ldsm4(a[mi], sbase + P_AH + (aRow0 + mi * 16) * RS2 + kOff + s * 32);
        #pragma unroll
        for (int nj = 0; nj < 2; nj++) {
            ldsm4(bh[nj], sbase + P_BH + (bRow0 + nj * 16) * RS2 + kOff + s * 32);
            ldsm4(bl[nj], sbase + P_BL + (bRow0 + nj * 16) * RS2 + kOff + s * 32);
        }
        #pragma unroll
        for (int mi = 0; mi < 4; mi++)
            #pragma unroll
            for (int ng = 0; ng < 4; ng++) {
                int nj = ng >> 1, g = ng & 1;
                mma_bf16(acc[mi][ng], a[mi], bh[nj][g], bh[nj][g + 2]);
                mma_bf16(acc[mi][ng], a[mi], bl[nj][g], bl[nj][g + 2]);
            }
    }
    #pragma unroll
    for (int s = 0; s < 2; s++) {
        uint32_t a[4][4], bh[2][4];
        #pragma unroll
        for (int mi = 0; mi < 4; mi++)
            ldsm4(a[mi], sbase + P_AL + (aRow0 + mi * 16) * RS2 + kOff + s * 32);
        #pragma unroll
        for (int nj = 0; nj < 2; nj++)
            ldsm4(bh[nj], sbase + P_BH + (bRow0 + nj * 16) * RS2 + kOff + s * 32);
        #pragma unroll
        for (int mi = 0; mi < 4; mi++)
            #pragma unroll
            for (int ng = 0; ng < 4; ng++) {
                int nj = ng >> 1, g = ng & 1;
                mma_bf16(acc[mi][ng], a[mi], bh[nj][g], bh[nj][g + 2]);
            }
    }
}

// ---------------------------------------------------------------- tiny kernels
__global__ void zero_kernel() {
    int i = blockIdx.x * blockDim.x + threadIdx.x;
    if (i < BS * SEQ) g_colsum[i] = 0.f;
}
__global__ void recip_kernel() {
    int i = blockIdx.x * blockDim.x + threadIdx.x;
    if (i < BS * SEQ) g_colsum[i] = WSCALE / g_colsum[i];
}

// ---------------------------------------------------------------------------
// Q/K f32 -> bf16 hi/lo padded blobs
// ---------------------------------------------------------------------------
__global__ __launch_bounds__(256)
void convert_qk(const float* __restrict__ Q, const float* __restrict__ K) {
    int tile = blockIdx.x, which = blockIdx.y, b = blockIdx.z;
    const float* src = (which ? K : Q) + ((size_t)b * SEQ + tile * 128) * DK;
    uint32_t* dst = (which ? g_K : g_Q) + (size_t)(b * NT + tile) * TS;

    for (int i = threadIdx.x; i < 2 * SEG; i += 256) {
        int ch = i / SEG, j = i % SEG;
        int row = j / 36, cp = j % 36;
        uint32_t h = 0, l = 0;
        if (cp < 32) {
            float2 v = *(const float2*)&src[row * DK + ch * 64 + cp * 2];
            bsplit2(v.x, v.y, h, l);
        }
        dst[ch * SEG + j] = h;
        dst[(2 + ch) * SEG + j] = l;
    }
}

// ---------------------------------------------------------------------------
// V f32 -> W blob: W[d][k] = (WSCALE*coef_k) * V[k][d], fp16 hi/lo image.
// ---------------------------------------------------------------------------
__global__ __launch_bounds__(256)
void convert_v(const float* __restrict__ V) {
    int kb = blockIdx.x, b = blockIdx.y;
    const float* Vb = V + (size_t)b * SEQ * DK;
    const float* Cb = g_colsum + b * SEQ;     // already WSCALE/colsum
    uint32_t* dst = g_W + (size_t)(b * NT + kb) * TS;

    for (int i = threadIdx.x; i < 2 * SEG; i += 256) {
        int ch = i / SEG, j = i % SEG;
        int d = j / 36, kp = j % 36;
        uint32_t h = 0, l = 0;
        if (kp < 32) {
            int k = kb * 128 + ch * 64 + 2 * kp;
            float v0 = Vb[(size_t)k * DK + d]       * Cb[k];
            float v1 = Vb[(size_t)(k + 1) * DK + d] * Cb[k + 1];
            hsplit2(v0, v1, h, l);
        }
        dst[ch * SEG + j] = h;
        dst[(2 + ch) * SEG + j] = l;
    }
}

// ---------------------------------------------------------------------------
// Kernel 1: S = Q.K^T (champion pipelined mainloop); epilogue exp -> fp16 P
// blob (smem-staged, single segment pair) + colsums via shuffle.
// ---------------------------------------------------------------------------
__global__ __launch_bounds__(256, 2)
void scores_hmma() {
    extern __shared__ char smem[];
    uint32_t sb = smem_u32(smem);
    int tid = threadIdx.x, lane = tid & 31, wid = tid >> 5;
    int warp_m = wid >> 2, warp_n = wid & 3;
    int kt = blockIdx.x, qt = blockIdx.y, b = blockIdx.z;

    const uint32_t* Qb = g_Q + (size_t)(b * NT + qt) * TS;
    const uint32_t* Kb = g_K + (size_t)(b * NT + kt) * TS;

    float acc[4][4][4];
    #pragma unroll
    for (int i = 0; i < 4; i++)
        #pragma unroll
        for (int j = 0; j < 4; j++)
            #pragma unroll
            for (int c = 0; c < 4; c++) acc[i][j][c] = 0.f;

    issue_sub(sb, Qb, Kb, 0, 0, tid);
    issue_sub(sb + STAGE_BYTES, Qb, Kb, 0, 1, tid);

    for (int s = 0; s < 4; s++) {
        if (s < 3) cp_wait1(); else cp_wait0();
        __syncthreads();
        mma_sub(sb + (s & 1) * STAGE_BYTES, acc, warp_m, warp_n, lane);
        __syncthreads();
        if (s + 2 < 4)
            issue_sub(sb + (s & 1) * STAGE_BYTES, Qb, Kb, (s + 2) >> 1, (s + 2) & 1, tid);
    }

    // Epilogue: exp -> fp16 staged into smem blob image ([q][k], 144B rows, 2 segs)
    float cs[4][2];
    #pragma unroll
    for (int ng = 0; ng < 4; ng++) { cs[ng][0] = 0.f; cs[ng][1] = 0.f; }

    #pragma unroll
    for (int mi = 0; mi < 4; mi++)
        #pragma unroll
        for (int ng = 0; ng < 4; ng++) {
            int R = warp_m * 64 + mi * 16 + (lane >> 2);
            int C = warp_n * 32 + ng * 8 + 2 * (lane & 3);
            int ch = C >> 6, cc = C & 63;
            #pragma unroll
            for (int rr = 0; rr < 2; rr++) {
                float p0 = __expf(acc[mi][ng][rr * 2]     * SCALE);
                float p1 = __expf(acc[mi][ng][rr * 2 + 1] * SCALE);
                cs[ng][0] += p0;
                cs[ng][1] += p1;
                int off = ch * 18432 + (R + rr * 8) * 144 + cc * 2;
                *(uint32_t*)(smem + off) = f16pack(p0, p1);
            }
        }

    // Shuffle-reduce colsums over the 8 lanes sharing a column, then atomic.
    #pragma unroll
    for (int ng = 0; ng < 4; ng++)
        #pragma unroll
        for (int c = 0; c < 2; c++) {
            float v = cs[ng][c];
            v += __shfl_xor_sync(0xFFFFFFFF, v, 4);
            v += __shfl_xor_sync(0xFFFFFFFF, v, 8);
            v += __shfl_xor_sync(0xFFFFFFFF, v, 16);
            if ((lane >> 2) == 0) {
                int col = warp_n * 32 + ng * 8 + 2 * (lane & 3) + c;
                atomicAdd(&g_colsum[b * SEQ + kt * 128 + col], v);
            }
        }
    __syncthreads();

    // Dump the staged fp16 blob (2 segments, coalesced)
    {
        size_t blob = ((size_t)(b * NT + qt) * NT + kt) * TSP2;
        uint4* d4 = (uint4*)(g_P + blob);
        const uint4* s4 = (const uint4*)smem;
        #pragma unroll
        for (int i = 0; i < 9; i++) d4[tid + i * 256] = s4[tid + i * 256];
    }
}

// ---------------------------------------------------------------------------
// Kernel 2: partial[split] = sum_k P~[q,k] * W~[k,d]  (2-pass fp16)
// Double-buffered 64-k chunks (A + W_hi + W_lo), occ 2, 8 steps.
// ---------------------------------------------------------------------------
__global__ __launch_bounds__(256, 2)
void out_hmma() {
    extern __shared__ char smem[];
    uint32_t sb = smem_u32(smem);
    int tid = threadIdx.x, lane = tid & 31, wid = tid >> 5;
    int warp_m = wid >> 2, warp_n = wid & 3;
    int qt = blockIdx.x, split = blockIdx.y, b = blockIdx.z;

    float acc[4][4][4];
    #pragma unroll
    for (int i = 0; i < 4; i++)
        #pragma unroll
        for (int j = 0; j < 4; j++)
            #pragma unroll
            for (int c = 0; c < 4; c++) acc[i][j][c] = 0.f;

    auto issue = [&](int step, int bi) {
        int kb = split * (NT / NS2) + (step >> 1);   // 4 k-tiles per split
        int h  = step & 1;                           // which 64-k half
        const uint32_t* Pb = g_P + ((size_t)(b * NT + qt) * NT + kb) * TSP2;
        const uint32_t* Wb = g_W + (size_t)(b * NT + kb) * TS;
        uint32_t base = sb + bi * OCHUNK;
        copy_seg_async(base + OC_A,  Pb + h * SEG, tid);
        copy_seg_async(base + OC_BH, Wb + h * SEG, tid);
        copy_seg_async(base + OC_BL, Wb + (2 + h) * SEG, tid);
        cp_commit();
    };

    issue(0, 0);
    issue(1, 1);

    int rIn  = (lane & 7) + ((lane >> 3) & 1) * 8;
    int kOff = (lane >> 4) * 16;
    int aRow0 = warp_m * 64 + rIn;
    int bRow0 = warp_n * 32 + rIn;

    const int NSTEP = 2 * (NT / NS2);   // 8
    for (int s2 = 0; s2 < NSTEP; s2++) {
        if (s2 < NSTEP - 1) cp_wait1(); else cp_wait0();
        __syncthreads();
        uint32_t cb = sb + (s2 & 1) * OCHUNK;
        #pragma unroll
        for (int s = 0; s < 4; s++) {
            uint32_t a[4][4], bh[2][4], bl[2][4];
            #pragma unroll
            for (int mi = 0; mi < 4; mi++)
                ldsm4(a[mi], cb + OC_A + (aRow0 + mi * 16) * 144 + kOff + s * 32);
            #pragma unroll
            for (int nj = 0; nj < 2; nj++) {
                ldsm4(bh[nj], cb + OC_BH + (bRow0 + nj * 16) * 144 + kOff + s * 32);
                ldsm4(bl[nj], cb + OC_BL + (bRow0 + nj * 16) * 144 + kOff + s * 32);
            }
            #pragma unroll
            for (int mi = 0; mi < 4; mi++)
                #pragma unroll
                for (int ng = 0; ng < 4; ng++) {
                    int nj = ng >> 1, g = ng & 1;
                    mma_f16(acc[mi][ng], a[mi], bh[nj][g], bh[nj][g + 2]);
                    mma_f16(acc[mi][ng], a[mi], bl[nj][g], bl[nj][g + 2]);
                }
        }
        __syncthreads();
        if (s2 + 2 < NSTEP) issue(s2 + 2, s2 & 1);
    }

    // Epilogue: f32 partial writes (coalesced float2)
    float* Pb = g_part + ((size_t)(split * BS + b) * SEQ + qt * 128) * DK;
    #pragma unroll
    for (int mi = 0; mi < 4; mi++)
        #pragma unroll
        for (int ng = 0; ng < 4; ng++) {
            int R = warp_m * 64 + mi * 16 + (lane >> 2);
            int C = warp_n * 32 + ng * 8 + 2 * (lane & 3);
            float2 v0 = make_float2(acc[mi][ng][0], acc[mi][ng][1]);
            float2 v1 = make_float2(acc[mi][ng][2], acc[mi][ng][3]);
            *(float2*)&Pb[(size_t)R * DK + C]       = v0;
            *(float2*)&Pb[(size_t)(R + 8) * DK + C] = v1;
        }
}

// ---------------------------------------------------------------------------
__global__ __launch_bounds__(256)
void combine_kernel(float* __restrict__ O) {
    const size_t N4 = (size_t)BS * SEQ * DK / 4;
    size_t i4 = (size_t)blockIdx.x * blockDim.x + threadIdx.x;
    if (i4 >= N4) return;
    const float4* P = (const float4*)g_part;
    float4 s = P[i4];
    #pragma unroll
    for (int sp = 1; sp < NS2; sp++) {
        float4 v = P[sp * N4 + i4];
        s.x += v.x; s.y += v.y; s.z += v.z; s.w += v.w;
    }
    s.x *= INV_WSCALE; s.y *= INV_WSCALE; s.z *= INV_WSCALE; s.w *= INV_WSCALE;
    ((float4*)O)[i4] = s;
}

// ---------------------------------------------------------------------------
extern "C" void kernel_launch(void* const* d_in, const int* in_sizes, int n_in,
                              void* d_out, int out_size) {
    const float* q = (const float*)d_in[0];
    const float* k = (const float*)d_in[1];
    const float* v = (const float*)d_in[2];
    float* out = (float*)d_out;

    cudaFuncSetAttribute(scores_hmma, cudaFuncAttributeMaxDynamicSharedMemorySize, SMEM_SCORES);
    cudaFuncSetAttribute(out_hmma,    cudaFuncAttributeMaxDynamicSharedMemorySize, SMEM_OUT);

    zero_kernel<<<(BS * SEQ + 511) / 512, 512>>>();
    convert_qk<<<dim3(NT, 2, BS), 256>>>(q, k);
    scores_hmma<<<dim3(NT, NT, BS), 256, SMEM_SCORES>>>();
    recip_kernel<<<(BS * SEQ + 511) / 512, 512>>>();
    convert_v<<<dim3(NT, BS), 256>>>(v);
    out_hmma<<<dim3(NT, NS2, BS), 256, SMEM_OUT>>>();
    combine_kernel<<<(BS * SEQ * DK / 4 + 255) / 256, 256>>>(out);
}

// round 16
// speedup vs baseline: 2.4176x; 1.1954x over previous
#include <cuda_runtime.h>
#include <cuda_bf16.h>
#include <cuda_fp16.h>
#include <cstdint>

#define BS 4
#define SEQ 4096
#define DK 128
#define SCALE 0.08838834764831843f   // 1/sqrt(128)
#define NT 32                        // 4096/128 tiles
#define NS2 8                        // split-K for output GEMM
#define SEG 4608                     // blob segment = 128 rows x 72 u32 (144B rows)
#define TS  (4*SEG)                  // K/W tile blob = [hi c0][hi c1][lo c0][lo c1]
#define TSP2 (2*SEG)                 // fp16 single blob = [c0][c1] (Q and P)
#define WSCALE 4096.0f
#define INV_WSCALE (1.0f/4096.0f)

// ---- scores pipeline stage (32-k subs): 3 parts (A, B_hi, B_lo) x 128 rows x 80B
#define RS2 80
#define PART_BYTES 10240
#define S_A  0
#define S_BH 10240
#define S_BL 20480
#define SSTAGE 30720
#define SMEM_SCORES 61440            // 2 stages, occ 2 (epilogue stages 36864B in-place)

// ---- out chunk (64-k): [A fp16][W_hi fp16][W_lo fp16] segments (row stride 144)
#define OC_A  0
#define OC_BH 18432
#define OC_BL 36864
#define OCHUNK 55296
#define SMEM_OUT 110592              // 2 chunks, occ 2

__device__ uint32_t g_Qh[(size_t)BS*NT*TSP2];     // fp16 Q (hi only)
__device__ uint32_t g_K[(size_t)BS*NT*TS];        // fp16 hi/lo K
__device__ uint32_t g_W[(size_t)BS*NT*TS];        // fp16 hi/lo of WSCALE*coef*V^T [d][k]
__device__ uint32_t g_P[(size_t)BS*NT*NT*TSP2];   // 151 MB fp16 P
__device__ float g_colsum[BS*SEQ];
__device__ float g_part[(size_t)NS2*BS*SEQ*DK];

// ------------------------------------------------------------------ helpers
__device__ __forceinline__ uint32_t smem_u32(const void* p) {
    uint32_t a;
    asm("{ .reg .u64 t; cvta.to.shared.u64 t, %1; cvt.u32.u64 %0, t; }" : "=r"(a) : "l"(p));
    return a;
}
__device__ __forceinline__ void ldsm4(uint32_t* r, uint32_t addr) {
    asm volatile("ldmatrix.sync.aligned.m8n8.x4.shared.b16 {%0,%1,%2,%3}, [%4];"
                 : "=r"(r[0]), "=r"(r[1]), "=r"(r[2]), "=r"(r[3]) : "r"(addr));
}
__device__ __forceinline__ void mma_f16(float* c, const uint32_t* a, uint32_t b0, uint32_t b1) {
    asm volatile("mma.sync.aligned.m16n8k16.row.col.f32.f16.f16.f32 "
                 "{%0,%1,%2,%3}, {%4,%5,%6,%7}, {%8,%9}, {%0,%1,%2,%3};"
                 : "+f"(c[0]), "+f"(c[1]), "+f"(c[2]), "+f"(c[3])
                 : "r"(a[0]), "r"(a[1]), "r"(a[2]), "r"(a[3]), "r"(b0), "r"(b1));
}
// fp16 hi/lo split
__device__ __forceinline__ void hsplit2(float x, float y, uint32_t& h, uint32_t& l) {
    asm("cvt.rn.f16x2.f32 %0, %1, %2;" : "=r"(h) : "f"(y), "f"(x));
    float xh, yh;
    asm("{ .reg .b16 lo, hi; mov.b32 {lo, hi}, %2;\n\t"
        "cvt.f32.f16 %0, lo; cvt.f32.f16 %1, hi; }" : "=f"(xh), "=f"(yh) : "r"(h));
    float xl = x - xh, yl = y - yh;
    asm("cvt.rn.f16x2.f32 %0, %1, %2;" : "=r"(l) : "f"(yl), "f"(xl));
}
__device__ __forceinline__ uint32_t f16pack(float x, float y) {
    uint32_t r;
    asm("cvt.rn.f16x2.f32 %0, %1, %2;" : "=r"(r) : "f"(y), "f"(x));
    return r;
}
__device__ __forceinline__ void cp16(uint32_t sdst, const void* gsrc) {
    asm volatile("cp.async.cg.shared.global [%0], [%1], 16;" :: "r"(sdst), "l"(gsrc) : "memory");
}
__device__ __forceinline__ void cp_commit() { asm volatile("cp.async.commit_group;" ::: "memory"); }
__device__ __forceinline__ void cp_wait0() { asm volatile("cp.async.wait_group 0;" ::: "memory"); }
__device__ __forceinline__ void cp_wait1() { asm volatile("cp.async.wait_group 1;" ::: "memory"); }

// ---- scores loader: one 32-k sub-chunk (3 parts x 128 rows x 64B) -> stage
__device__ __forceinline__ void issue_sub(uint32_t stage, const uint32_t* Qb, const uint32_t* Kb,
                                          int ch, int h, int tid) {
    const uint32_t* segs[3] = { Qb + ch * SEG, Kb + ch * SEG, Kb + (2 + ch) * SEG };
    #pragma unroll
    for (int i = 0; i < 6; i++) {
        int t = tid + i * 256;
        int part = t >> 9;              // uniform per i: 0,0,1,1,2,2
        int w = t & 511, row = w >> 2, q = w & 3;
        const char* src = (const char*)segs[part] + row * 144 + h * 64 + q * 16;
        cp16(stage + part * PART_BYTES + row * RS2 + q * 16, src);
    }
    cp_commit();
}
// ---- one full 18432B segment -> smem
__device__ __forceinline__ void copy_seg_async(uint32_t sdst, const uint32_t* src, int tid) {
    #pragma unroll
    for (int i = 0; i < 5; i++) {
        int j = tid + i * 256;
        if (j < 1152) cp16(sdst + j * 16, (const char*)src + j * 16);
    }
}

// ---------------------------------------------------------------------------
// 2-pass fp16 GEMM over a 32-k stage (scores): acc += A*(B_hi+B_lo)^T.
// ---------------------------------------------------------------------------
__device__ __forceinline__ void mma_sub(uint32_t sbase, float acc[4][4][4],
                                        int warp_m, int warp_n, int lane) {
    int rIn  = (lane & 7) + ((lane >> 3) & 1) * 8;
    int kOff = (lane >> 4) * 16;
    int aRow0 = warp_m * 64 + rIn;
    int bRow0 = warp_n * 32 + rIn;

    #pragma unroll
    for (int s = 0; s < 2; s++) {
        uint32_t a[4][4], bh[2][4], bl[2][4];
        #pragma unroll
        for (int mi = 0; mi < 4; mi++)
            ldsm4(a[mi], sbase + S_A + (aRow0 + mi * 16) * RS2 + kOff + s * 32);
        #pragma unroll
        for (int nj = 0; nj < 2; nj++) {
            ldsm4(bh[nj], sbase + S_BH + (bRow0 + nj * 16) * RS2 + kOff + s * 32);
            ldsm4(bl[nj], sbase + S_BL + (bRow0 + nj * 16) * RS2 + kOff + s * 32);
        }
        #pragma unroll
        for (int mi = 0; mi < 4; mi++)
            #pragma unroll
            for (int ng = 0; ng < 4; ng++) {
                int nj = ng >> 1, g = ng & 1;
                mma_f16(acc[mi][ng], a[mi], bh[nj][g], bh[nj][g + 2]);
                mma_f16(acc[mi][ng], a[mi], bl[nj][g], bl[nj][g + 2]);
            }
    }
}

// ---------------------------------------------------------------- tiny kernels
__global__ void zero_kernel() {
    int i = blockIdx.x * blockDim.x + threadIdx.x;
    if (i < BS * SEQ) g_colsum[i] = 0.f;
}
__global__ void recip_kernel() {
    int i = blockIdx.x * blockDim.x + threadIdx.x;
    if (i < BS * SEQ) g_colsum[i] = WSCALE / g_colsum[i];
}

// ---------------------------------------------------------------------------
// Q f32 -> fp16 single blob; K f32 -> fp16 hi/lo blob.
// ---------------------------------------------------------------------------
__global__ __launch_bounds__(256)
void convert_qk(const float* __restrict__ Q, const float* __restrict__ K) {
    int tile = blockIdx.x, which = blockIdx.y, b = blockIdx.z;
    const float* src = (which ? K : Q) + ((size_t)b * SEQ + tile * 128) * DK;

    if (which == 0) {
        uint32_t* dst = g_Qh + (size_t)(b * NT + tile) * TSP2;
        for (int i = threadIdx.x; i < 2 * SEG; i += 256) {
            int ch = i / SEG, j = i % SEG;
            int row = j / 36, cp = j % 36;
            uint32_t h = 0;
            if (cp < 32) {
                float2 v = *(const float2*)&src[row * DK + ch * 64 + cp * 2];
                h = f16pack(v.x, v.y);
            }
            dst[ch * SEG + j] = h;
        }
    } else {
        uint32_t* dst = g_K + (size_t)(b * NT + tile) * TS;
        for (int i = threadIdx.x; i < 2 * SEG; i += 256) {
            int ch = i / SEG, j = i % SEG;
            int row = j / 36, cp = j % 36;
            uint32_t h = 0, l = 0;
            if (cp < 32) {
                float2 v = *(const float2*)&src[row * DK + ch * 64 + cp * 2];
                hsplit2(v.x, v.y, h, l);
            }
            dst[ch * SEG + j] = h;
            dst[(2 + ch) * SEG + j] = l;
        }
    }
}

// ---------------------------------------------------------------------------
// V f32 -> W blob: W[d][k] = (WSCALE*coef_k) * V[k][d], fp16 hi/lo image.
// ---------------------------------------------------------------------------
__global__ __launch_bounds__(256)
void convert_v(const float* __restrict__ V) {
    int kb = blockIdx.x, b = blockIdx.y;
    const float* Vb = V + (size_t)b * SEQ * DK;
    const float* Cb = g_colsum + b * SEQ;     // already WSCALE/colsum
    uint32_t* dst = g_W + (size_t)(b * NT + kb) * TS;

    for (int i = threadIdx.x; i < 2 * SEG; i += 256) {
        int ch = i / SEG, j = i % SEG;
        int d = j / 36, kp = j % 36;
        uint32_t h = 0, l = 0;
        if (kp < 32) {
            int k = kb * 128 + ch * 64 + 2 * kp;
            float v0 = Vb[(size_t)k * DK + d]       * Cb[k];
            float v1 = Vb[(size_t)(k + 1) * DK + d] * Cb[k + 1];
            hsplit2(v0, v1, h, l);
        }
        dst[ch * SEG + j] = h;
        dst[(2 + ch) * SEG + j] = l;
    }
}

// ---------------------------------------------------------------------------
// Kernel 1: S = Q.K^T (2-pass fp16, pipelined); epilogue exp -> fp16 P blob
// (smem-staged) + colsums via shuffle.
// ---------------------------------------------------------------------------
__global__ __launch_bounds__(256, 2)
void scores_hmma() {
    extern __shared__ char smem[];
    uint32_t sb = smem_u32(smem);
    int tid = threadIdx.x, lane = tid & 31, wid = tid >> 5;
    int warp_m = wid >> 2, warp_n = wid & 3;
    int kt = blockIdx.x, qt = blockIdx.y, b = blockIdx.z;

    const uint32_t* Qb = g_Qh + (size_t)(b * NT + qt) * TSP2;
    const uint32_t* Kb = g_K  + (size_t)(b * NT + kt) * TS;

    float acc[4][4][4];
    #pragma unroll
    for (int i = 0; i < 4; i++)
        #pragma unroll
        for (int j = 0; j < 4; j++)
            #pragma unroll
            for (int c = 0; c < 4; c++) acc[i][j][c] = 0.f;

    issue_sub(sb, Qb, Kb, 0, 0, tid);
    issue_sub(sb + SSTAGE, Qb, Kb, 0, 1, tid);

    for (int s = 0; s < 4; s++) {
        if (s < 3) cp_wait1(); else cp_wait0();
        __syncthreads();
        mma_sub(sb + (s & 1) * SSTAGE, acc, warp_m, warp_n, lane);
        __syncthreads();
        if (s + 2 < 4)
            issue_sub(sb + (s & 1) * SSTAGE, Qb, Kb, (s + 2) >> 1, (s + 2) & 1, tid);
    }

    // Epilogue: exp -> fp16 staged into smem blob image ([q][k], 144B rows, 2 segs)
    float cs[4][2];
    #pragma unroll
    for (int ng = 0; ng < 4; ng++) { cs[ng][0] = 0.f; cs[ng][1] = 0.f; }

    #pragma unroll
    for (int mi = 0; mi < 4; mi++)
        #pragma unroll
        for (int ng = 0; ng < 4; ng++) {
            int R = warp_m * 64 + mi * 16 + (lane >> 2);
            int C = warp_n * 32 + ng * 8 + 2 * (lane & 3);
            int ch = C >> 6, cc = C & 63;
            #pragma unroll
            for (int rr = 0; rr < 2; rr++) {
                float p0 = __expf(acc[mi][ng][rr * 2]     * SCALE);
                float p1 = __expf(acc[mi][ng][rr * 2 + 1] * SCALE);
                cs[ng][0] += p0;
                cs[ng][1] += p1;
                int off = ch * 18432 + (R + rr * 8) * 144 + cc * 2;
                *(uint32_t*)(smem + off) = f16pack(p0, p1);
            }
        }

    // Shuffle-reduce colsums over the 8 lanes sharing a column, then atomic.
    #pragma unroll
    for (int ng = 0; ng < 4; ng++)
        #pragma unroll
        for (int c = 0; c < 2; c++) {
            float v = cs[ng][c];
            v += __shfl_xor_sync(0xFFFFFFFF, v, 4);
            v += __shfl_xor_sync(0xFFFFFFFF, v, 8);
            v += __shfl_xor_sync(0xFFFFFFFF, v, 16);
            if ((lane >> 2) == 0) {
                int col = warp_n * 32 + ng * 8 + 2 * (lane & 3) + c;
                atomicAdd(&g_colsum[b * SEQ + kt * 128 + col], v);
            }
        }
    __syncthreads();

    // Dump the staged fp16 blob (2 segments, coalesced)
    {
        size_t blob = ((size_t)(b * NT + qt) * NT + kt) * TSP2;
        uint4* d4 = (uint4*)(g_P + blob);
        const uint4* s4 = (const uint4*)smem;
        #pragma unroll
        for (int i = 0; i < 9; i++) d4[tid + i * 256] = s4[tid + i * 256];
    }
}

// ---------------------------------------------------------------------------
// Kernel 2: partial[split] = sum_k P~[q,k] * W~[k,d]  (2-pass fp16)
// Double-buffered 64-k chunks (A + W_hi + W_lo), occ 2, 8 steps.
// ---------------------------------------------------------------------------
__global__ __launch_bounds__(256, 2)
void out_hmma() {
    extern __shared__ char smem[];
    uint32_t sb = smem_u32(smem);
    int tid = threadIdx.x, lane = tid & 31, wid = tid >> 5;
    int warp_m = wid >> 2, warp_n = wid & 3;
    int qt = blockIdx.x, split = blockIdx.y, b = blockIdx.z;

    float acc[4][4][4];
    #pragma unroll
    for (int i = 0; i < 4; i++)
        #pragma unroll
        for (int j = 0; j < 4; j++)
            #pragma unroll
            for (int c = 0; c < 4; c++) acc[i][j][c] = 0.f;

    auto issue = [&](int step, int bi) {
        int kb = split * (NT / NS2) + (step >> 1);
        int h  = step & 1;
        const uint32_t* Pb = g_P + ((size_t)(b * NT + qt) * NT + kb) * TSP2;
        const uint32_t* Wb = g_W + (size_t)(b * NT + kb) * TS;
        uint32_t base = sb + bi * OCHUNK;
        copy_seg_async(base + OC_A,  Pb + h * SEG, tid);
        copy_seg_async(base + OC_BH, Wb + h * SEG, tid);
        copy_seg_async(base + OC_BL, Wb + (2 + h) * SEG, tid);
        cp_commit();
    };

    issue(0, 0);
    issue(1, 1);

    int rIn  = (lane & 7) + ((lane >> 3) & 1) * 8;
    int kOff = (lane >> 4) * 16;
    int aRow0 = warp_m * 64 + rIn;
    int bRow0 = warp_n * 32 + rIn;

    const int NSTEP = 2 * (NT / NS2);   // 8
    for (int s2 = 0; s2 < NSTEP; s2++) {
        if (s2 < NSTEP - 1) cp_wait1(); else cp_wait0();
        __syncthreads();
        uint32_t cb = sb + (s2 & 1) * OCHUNK;
        #pragma unroll
        for (int s = 0; s < 4; s++) {
            uint32_t a[4][4], bh[2][4], bl[2][4];
            #pragma unroll
            for (int mi = 0; mi < 4; mi++)
                ldsm4(a[mi], cb + OC_A + (aRow0 + mi * 16) * 144 + kOff + s * 32);
            #pragma unroll
            for (int nj = 0; nj < 2; nj++) {
                ldsm4(bh[nj], cb + OC_BH + (bRow0 + nj * 16) * 144 + kOff + s * 32);
                ldsm4(bl[nj], cb + OC_BL + (bRow0 + nj * 16) * 144 + kOff + s * 32);
            }
            #pragma unroll
            for (int mi = 0; mi < 4; mi++)
                #pragma unroll
                for (int ng = 0; ng < 4; ng++) {
                    int nj = ng >> 1, g = ng & 1;
                    mma_f16(acc[mi][ng], a[mi], bh[nj][g], bh[nj][g + 2]);
                    mma_f16(acc[mi][ng], a[mi], bl[nj][g], bl[nj][g + 2]);
                }
        }
        __syncthreads();
        if (s2 + 2 < NSTEP) issue(s2 + 2, s2 & 1);
    }

    // Epilogue: f32 partial writes (coalesced float2)
    float* Pb = g_part + ((size_t)(split * BS + b) * SEQ + qt * 128) * DK;
    #pragma unroll
    for (int mi = 0; mi < 4; mi++)
        #pragma unroll
        for (int ng = 0; ng < 4; ng++) {
            int R = warp_m * 64 + mi * 16 + (lane >> 2);
            int C = warp_n * 32 + ng * 8 + 2 * (lane & 3);
            float2 v0 = make_float2(acc[mi][ng][0], acc[mi][ng][1]);
            float2 v1 = make_float2(acc[mi][ng][2], acc[mi][ng][3]);
            *(float2*)&Pb[(size_t)R * DK + C]       = v0;
            *(float2*)&Pb[(size_t)(R + 8) * DK + C] = v1;
        }
}

// ---------------------------------------------------------------------------
__global__ __launch_bounds__(256)
void combine_kernel(float* __restrict__ O) {
    const size_t N4 = (size_t)BS * SEQ * DK / 4;
    size_t i4 = (size_t)blockIdx.x * blockDim.x + threadIdx.x;
    if (i4 >= N4) return;
    const float4* P = (const float4*)g_part;
    float4 s = P[i4];
    #pragma unroll
    for (int sp = 1; sp < NS2; sp++) {
        float4 v = P[sp * N4 + i4];
        s.x += v.x; s.y += v.y; s.z += v.z; s.w += v.w;
    }
    s.x *= INV_WSCALE; s.y *= INV_WSCALE; s.z *= INV_WSCALE; s.w *= INV_WSCALE;
    ((float4*)O)[i4] = s;
}

// ---------------------------------------------------------------------------
extern "C" void kernel_launch(void* const* d_in, const int* in_sizes, int n_in,
                              void* d_out, int out_size) {
    const float* q = (const float*)d_in[0];
    const float* k = (const float*)d_in[1];
    const float* v = (const float*)d_in[2];
    float* out = (float*)d_out;

    cudaFuncSetAttribute(scores_hmma, cudaFuncAttributeMaxDynamicSharedMemorySize, SMEM_SCORES);
    cudaFuncSetAttribute(out_hmma,    cudaFuncAttributeMaxDynamicSharedMemorySize, SMEM_OUT);

    zero_kernel<<<(BS * SEQ + 511) / 512, 512>>>();
    convert_qk<<<dim3(NT, 2, BS), 256>>>(q, k);
    scores_hmma<<<dim3(NT, NT, BS), 256, SMEM_SCORES>>>();
    recip_kernel<<<(BS * SEQ + 511) / 512, 512>>>();
    convert_v<<<dim3(NT, BS), 256>>>(v);
    out_hmma<<<dim3(NT, NS2, BS), 256, SMEM_OUT>>>();
    combine_kernel<<<(BS * SEQ * DK / 4 + 255) / 256, 256>>>(out);
}

// round 17
// speedup vs baseline: 3.3676x; 1.3929x over previous
#include <cuda_runtime.h>
#include <cuda_fp16.h>
#include <cstdint>

#define BS 4
#define SEQ 4096
#define DK 128
#define SCALE 0.08838834764831843f   // 1/sqrt(128)
#define NT 32                        // 4096/128 tiles
#define NS2 8                        // split-K for output GEMM
#define SEG 4608                     // blob segment = 128 rows x 72 u32 (144B rows)
#define TSP2 (2*SEG)                 // fp16 tile blob = [c0][c1]
#define WSCALE 4096.0f
#define INV_WSCALE (1.0f/4096.0f)

// ---- scores pipeline stage (32-k subs): 2 parts (A, B) x 128 rows x 80B
#define RS2 80
#define PART_BYTES 10240
#define S_A  0
#define S_B  10240
#define SSTAGE 20480
#define SMEM_SCORES 40960            // 2 stages, occ 2 (epilogue stages 36864B in-place... no:
                                     // epilogue needs 36864B; SMEM is 40960B total -> fits)

// ---- out chunk (64-k): [A fp16][W fp16] segments (row stride 144)
#define OC_A  0
#define OC_B  18432
#define OCHUNK 36864
#define SMEM_OUT 73728               // 2 chunks, occ 2

__device__ uint32_t g_Qh[(size_t)BS*NT*TSP2];     // fp16 Q
__device__ uint32_t g_Kh[(size_t)BS*NT*TSP2];     // fp16 K
__device__ uint32_t g_W[(size_t)BS*NT*TSP2];      // fp16 WSCALE*coef*V^T [d][k]
__device__ uint32_t g_P[(size_t)BS*NT*NT*TSP2];   // 151 MB fp16 P
__device__ float g_colsum[BS*SEQ];
__device__ float g_part[(size_t)NS2*BS*SEQ*DK];

// ------------------------------------------------------------------ helpers
__device__ __forceinline__ uint32_t smem_u32(const void* p) {
    uint32_t a;
    asm("{ .reg .u64 t; cvta.to.shared.u64 t, %1; cvt.u32.u64 %0, t; }" : "=r"(a) : "l"(p));
    return a;
}
__device__ __forceinline__ void ldsm4(uint32_t* r, uint32_t addr) {
    asm volatile("ldmatrix.sync.aligned.m8n8.x4.shared.b16 {%0,%1,%2,%3}, [%4];"
                 : "=r"(r[0]), "=r"(r[1]), "=r"(r[2]), "=r"(r[3]) : "r"(addr));
}
__device__ __forceinline__ void mma_f16(float* c, const uint32_t* a, uint32_t b0, uint32_t b1) {
    asm volatile("mma.sync.aligned.m16n8k16.row.col.f32.f16.f16.f32 "
                 "{%0,%1,%2,%3}, {%4,%5,%6,%7}, {%8,%9}, {%0,%1,%2,%3};"
                 : "+f"(c[0]), "+f"(c[1]), "+f"(c[2]), "+f"(c[3])
                 : "r"(a[0]), "r"(a[1]), "r"(a[2]), "r"(a[3]), "r"(b0), "r"(b1));
}
__device__ __forceinline__ uint32_t f16pack(float x, float y) {
    uint32_t r;
    asm("cvt.rn.f16x2.f32 %0, %1, %2;" : "=r"(r) : "f"(y), "f"(x));
    return r;
}
__device__ __forceinline__ void cp16(uint32_t sdst, const void* gsrc) {
    asm volatile("cp.async.cg.shared.global [%0], [%1], 16;" :: "r"(sdst), "l"(gsrc) : "memory");
}
__device__ __forceinline__ void cp_commit() { asm volatile("cp.async.commit_group;" ::: "memory"); }
__device__ __forceinline__ void cp_wait0() { asm volatile("cp.async.wait_group 0;" ::: "memory"); }
__device__ __forceinline__ void cp_wait1() { asm volatile("cp.async.wait_group 1;" ::: "memory"); }

// ---- scores loader: one 32-k sub-chunk (2 parts x 128 rows x 64B) -> stage
__device__ __forceinline__ void issue_sub(uint32_t stage, const uint32_t* Qb, const uint32_t* Kb,
                                          int ch, int h, int tid) {
    const uint32_t* segs[2] = { Qb + ch * SEG, Kb + ch * SEG };
    #pragma unroll
    for (int i = 0; i < 4; i++) {
        int t = tid + i * 256;
        int part = t >> 9;              // uniform per i: 0,0,1,1
        int w = t & 511, row = w >> 2, q = w & 3;
        const char* src = (const char*)segs[part] + row * 144 + h * 64 + q * 16;
        cp16(stage + part * PART_BYTES + row * RS2 + q * 16, src);
    }
    cp_commit();
}
// ---- one full 18432B segment -> smem
__device__ __forceinline__ void copy_seg_async(uint32_t sdst, const uint32_t* src, int tid) {
    #pragma unroll
    for (int i = 0; i < 5; i++) {
        int j = tid + i * 256;
        if (j < 1152) cp16(sdst + j * 16, (const char*)src + j * 16);
    }
}

// ---------------------------------------------------------------------------
// 1-pass fp16 GEMM over a 32-k stage (scores): acc += A*B^T.
// ---------------------------------------------------------------------------
__device__ __forceinline__ void mma_sub(uint32_t sbase, float acc[4][4][4],
                                        int warp_m, int warp_n, int lane) {
    int rIn  = (lane & 7) + ((lane >> 3) & 1) * 8;
    int kOff = (lane >> 4) * 16;
    int aRow0 = warp_m * 64 + rIn;
    int bRow0 = warp_n * 32 + rIn;

    #pragma unroll
    for (int s = 0; s < 2; s++) {
        uint32_t a[4][4], bh[2][4];
        #pragma unroll
        for (int mi = 0; mi < 4; mi++)
            ldsm4(a[mi], sbase + S_A + (aRow0 + mi * 16) * RS2 + kOff + s * 32);
        #pragma unroll
        for (int nj = 0; nj < 2; nj++)
            ldsm4(bh[nj], sbase + S_B + (bRow0 + nj * 16) * RS2 + kOff + s * 32);
        #pragma unroll
        for (int mi = 0; mi < 4; mi++)
            #pragma unroll
            for (int ng = 0; ng < 4; ng++) {
                int nj = ng >> 1, g = ng & 1;
                mma_f16(acc[mi][ng], a[mi], bh[nj][g], bh[nj][g + 2]);
            }
    }
}

// ---------------------------------------------------------------- tiny kernels
__global__ void zero_kernel() {
    int i = blockIdx.x * blockDim.x + threadIdx.x;
    if (i < BS * SEQ) g_colsum[i] = 0.f;
}
__global__ void recip_kernel() {
    int i = blockIdx.x * blockDim.x + threadIdx.x;
    if (i < BS * SEQ) g_colsum[i] = WSCALE / g_colsum[i];
}

// ---------------------------------------------------------------------------
// Q/K f32 -> fp16 single blobs
// ---------------------------------------------------------------------------
__global__ __launch_bounds__(256)
void convert_qk(const float* __restrict__ Q, const float* __restrict__ K) {
    int tile = blockIdx.x, which = blockIdx.y, b = blockIdx.z;
    const float* src = (which ? K : Q) + ((size_t)b * SEQ + tile * 128) * DK;
    uint32_t* dst = (which ? g_Kh : g_Qh) + (size_t)(b * NT + tile) * TSP2;

    for (int i = threadIdx.x; i < 2 * SEG; i += 256) {
        int ch = i / SEG, j = i % SEG;
        int row = j / 36, cp = j % 36;
        uint32_t h = 0;
        if (cp < 32) {
            float2 v = *(const float2*)&src[row * DK + ch * 64 + cp * 2];
            h = f16pack(v.x, v.y);
        }
        dst[ch * SEG + j] = h;
    }
}

// ---------------------------------------------------------------------------
// V f32 -> W blob: W[d][k] = (WSCALE*coef_k) * V[k][d], fp16 single image.
// ---------------------------------------------------------------------------
__global__ __launch_bounds__(256)
void convert_v(const float* __restrict__ V) {
    int kb = blockIdx.x, b = blockIdx.y;
    const float* Vb = V + (size_t)b * SEQ * DK;
    const float* Cb = g_colsum + b * SEQ;     // already WSCALE/colsum
    uint32_t* dst = g_W + (size_t)(b * NT + kb) * TSP2;

    for (int i = threadIdx.x; i < 2 * SEG; i += 256) {
        int ch = i / SEG, j = i % SEG;
        int d = j / 36, kp = j % 36;
        uint32_t h = 0;
        if (kp < 32) {
            int k = kb * 128 + ch * 64 + 2 * kp;
            float v0 = Vb[(size_t)k * DK + d]       * Cb[k];
            float v1 = Vb[(size_t)(k + 1) * DK + d] * Cb[k + 1];
            h = f16pack(v0, v1);
        }
        dst[ch * SEG + j] = h;
    }
}

// ---------------------------------------------------------------------------
// Kernel 1: S = Q.K^T (1-pass fp16, pipelined); epilogue exp -> fp16 P blob
// (smem-staged) + colsums via shuffle.
// ---------------------------------------------------------------------------
__global__ __launch_bounds__(256, 2)
void scores_hmma() {
    extern __shared__ char smem[];
    uint32_t sb = smem_u32(smem);
    int tid = threadIdx.x, lane = tid & 31, wid = tid >> 5;
    int warp_m = wid >> 2, warp_n = wid & 3;
    int kt = blockIdx.x, qt = blockIdx.y, b = blockIdx.z;

    const uint32_t* Qb = g_Qh + (size_t)(b * NT + qt) * TSP2;
    const uint32_t* Kb = g_Kh + (size_t)(b * NT + kt) * TSP2;

    float acc[4][4][4];
    #pragma unroll
    for (int i = 0; i < 4; i++)
        #pragma unroll
        for (int j = 0; j < 4; j++)
            #pragma unroll
            for (int c = 0; c < 4; c++) acc[i][j][c] = 0.f;

    issue_sub(sb, Qb, Kb, 0, 0, tid);
    issue_sub(sb + SSTAGE, Qb, Kb, 0, 1, tid);

    for (int s = 0; s < 4; s++) {
        if (s < 3) cp_wait1(); else cp_wait0();
        __syncthreads();
        mma_sub(sb + (s & 1) * SSTAGE, acc, warp_m, warp_n, lane);
        __syncthreads();
        if (s + 2 < 4)
            issue_sub(sb + (s & 1) * SSTAGE, Qb, Kb, (s + 2) >> 1, (s + 2) & 1, tid);
    }

    // Epilogue: exp -> fp16 staged into smem blob image ([q][k], 144B rows, 2 segs)
    float cs[4][2];
    #pragma unroll
    for (int ng = 0; ng < 4; ng++) { cs[ng][0] = 0.f; cs[ng][1] = 0.f; }

    #pragma unroll
    for (int mi = 0; mi < 4; mi++)
        #pragma unroll
        for (int ng = 0; ng < 4; ng++) {
            int R = warp_m * 64 + mi * 16 + (lane >> 2);
            int C = warp_n * 32 + ng * 8 + 2 * (lane & 3);
            int ch = C >> 6, cc = C & 63;
            #pragma unroll
            for (int rr = 0; rr < 2; rr++) {
                float p0 = __expf(acc[mi][ng][rr * 2]     * SCALE);
                float p1 = __expf(acc[mi][ng][rr * 2 + 1] * SCALE);
                cs[ng][0] += p0;
                cs[ng][1] += p1;
                int off = ch * 18432 + (R + rr * 8) * 144 + cc * 2;
                *(uint32_t*)(smem + off) = f16pack(p0, p1);
            }
        }

    // Shuffle-reduce colsums over the 8 lanes sharing a column, then atomic.
    #pragma unroll
    for (int ng = 0; ng < 4; ng++)
        #pragma unroll
        for (int c = 0; c < 2; c++) {
            float v = cs[ng][c];
            v += __shfl_xor_sync(0xFFFFFFFF, v, 4);
            v += __shfl_xor_sync(0xFFFFFFFF, v, 8);
            v += __shfl_xor_sync(0xFFFFFFFF, v, 16);
            if ((lane >> 2) == 0) {
                int col = warp_n * 32 + ng * 8 + 2 * (lane & 3) + c;
                atomicAdd(&g_colsum[b * SEQ + kt * 128 + col], v);
            }
        }
    __syncthreads();

    // Dump the staged fp16 blob (2 segments, coalesced)
    {
        size_t blob = ((size_t)(b * NT + qt) * NT + kt) * TSP2;
        uint4* d4 = (uint4*)(g_P + blob);
        const uint4* s4 = (const uint4*)smem;
        #pragma unroll
        for (int i = 0; i < 9; i++) d4[tid + i * 256] = s4[tid + i * 256];
    }
}

// ---------------------------------------------------------------------------
// Kernel 2: partial[split] = sum_k P~[q,k] * W~[k,d]  (1-pass fp16)
// Double-buffered 64-k chunks (A + W), occ 2, 8 steps.
// ---------------------------------------------------------------------------
__global__ __launch_bounds__(256, 2)
void out_hmma() {
    extern __shared__ char smem[];
    uint32_t sb = smem_u32(smem);
    int tid = threadIdx.x, lane = tid & 31, wid = tid >> 5;
    int warp_m = wid >> 2, warp_n = wid & 3;
    int qt = blockIdx.x, split = blockIdx.y, b = blockIdx.z;

    float acc[4][4][4];
    #pragma unroll
    for (int i = 0; i < 4; i++)
        #pragma unroll
        for (int j = 0; j < 4; j++)
            #pragma unroll
            for (int c = 0; c < 4; c++) acc[i][j][c] = 0.f;

    auto issue = [&](int step, int bi) {
        int kb = split * (NT / NS2) + (step >> 1);
        int h  = step & 1;
        const uint32_t* Pb = g_P + ((size_t)(b * NT + qt) * NT + kb) * TSP2;
        const uint32_t* Wb = g_W + (size_t)(b * NT + kb) * TSP2;
        uint32_t base = sb + bi * OCHUNK;
        copy_seg_async(base + OC_A, Pb + h * SEG, tid);
        copy_seg_async(base + OC_B, Wb + h * SEG, tid);
        cp_commit();
    };

    issue(0, 0);
    issue(1, 1);

    int rIn  = (lane & 7) + ((lane >> 3) & 1) * 8;
    int kOff = (lane >> 4) * 16;
    int aRow0 = warp_m * 64 + rIn;
    int bRow0 = warp_n * 32 + rIn;

    const int NSTEP = 2 * (NT / NS2);   // 8
    for (int s2 = 0; s2 < NSTEP; s2++) {
        if (s2 < NSTEP - 1) cp_wait1(); else cp_wait0();
        __syncthreads();
        uint32_t cb = sb + (s2 & 1) * OCHUNK;
        #pragma unroll
        for (int s = 0; s < 4; s++) {
            uint32_t a[4][4], bh[2][4];
            #pragma unroll
            for (int mi = 0; mi < 4; mi++)
                ldsm4(a[mi], cb + OC_A + (aRow0 + mi * 16) * 144 + kOff + s * 32);
            #pragma unroll
            for (int nj = 0; nj < 2; nj++)
                ldsm4(bh[nj], cb + OC_B + (bRow0 + nj * 16) * 144 + kOff + s * 32);
            #pragma unroll
            for (int mi = 0; mi < 4; mi++)
                #pragma unroll
                for (int ng = 0; ng < 4; ng++) {
                    int nj = ng >> 1, g = ng & 1;
                    mma_f16(acc[mi][ng], a[mi], bh[nj][g], bh[nj][g + 2]);
                }
        }
        __syncthreads();
        if (s2 + 2 < NSTEP) issue(s2 + 2, s2 & 1);
    }

    // Epilogue: f32 partial writes (coalesced float2)
    float* Pb = g_part + ((size_t)(split * BS + b) * SEQ + qt * 128) * DK;
    #pragma unroll
    for (int mi = 0; mi < 4; mi++)
        #pragma unroll
        for (int ng = 0; ng < 4; ng++) {
            int R = warp_m * 64 + mi * 16 + (lane >> 2);
            int C = warp_n * 32 + ng * 8 + 2 * (lane & 3);
            float2 v0 = make_float2(acc[mi][ng][0], acc[mi][ng][1]);
            float2 v1 = make_float2(acc[mi][ng][2], acc[mi][ng][3]);
            *(float2*)&Pb[(size_t)R * DK + C]       = v0;
            *(float2*)&Pb[(size_t)(R + 8) * DK + C] = v1;
        }
}

// ---------------------------------------------------------------------------
__global__ __launch_bounds__(256)
void combine_kernel(float* __restrict__ O) {
    const size_t N4 = (size_t)BS * SEQ * DK / 4;
    size_t i4 = (size_t)blockIdx.x * blockDim.x + threadIdx.x;
    if (i4 >= N4) return;
    const float4* P = (const float4*)g_part;
    float4 s = P[i4];
    #pragma unroll
    for (int sp = 1; sp < NS2; sp++) {
        float4 v = P[sp * N4 + i4];
        s.x += v.x; s.y += v.y; s.z += v.z; s.w += v.w;
    }
    s.x *= INV_WSCALE; s.y *= INV_WSCALE; s.z *= INV_WSCALE; s.w *= INV_WSCALE;
    ((float4*)O)[i4] = s;
}

// ---------------------------------------------------------------------------
extern "C" void kernel_launch(void* const* d_in, const int* in_sizes, int n_in,
                              void* d_out, int out_size) {
    const float* q = (const float*)d_in[0];
    const float* k = (const float*)d_in[1];
    const float* v = (const float*)d_in[2];
    float* out = (float*)d_out;

    cudaFuncSetAttribute(scores_hmma, cudaFuncAttributeMaxDynamicSharedMemorySize, SMEM_SCORES);
    cudaFuncSetAttribute(out_hmma,    cudaFuncAttributeMaxDynamicSharedMemorySize, SMEM_OUT);

    zero_kernel<<<(BS * SEQ + 511) / 512, 512>>>();
    convert_qk<<<dim3(NT, 2, BS), 256>>>(q, k);
    scores_hmma<<<dim3(NT, NT, BS), 256, SMEM_SCORES>>>();
    recip_kernel<<<(BS * SEQ + 511) / 512, 512>>>();
    convert_v<<<dim3(NT, BS), 256>>>(v);
    out_hmma<<<dim3(NT, NS2, BS), 256, SMEM_OUT>>>();
    combine_kernel<<<(BS * SEQ * DK / 4 + 255) / 256, 256>>>(out);
}